// round 1
// baseline (speedup 1.0000x reference)
#include <cuda_runtime.h>
#include <cuda_bf16.h>

#define NN 50000
#define EE 250000
#define TT 4
#define HD 128
#define DD 64

// -------- scratch (static device globals; no allocations) --------
__device__ float    d_feat[(size_t)TT * NN * HD];   // (T,N,H*D)  102.4 MB
__device__ float    d_el[TT * NN * 2];
__device__ float    d_er[TT * NN * 2];
__device__ unsigned d_emax[TT * NN * 2];            // encoded-float max
__device__ float    d_denom[TT * NN * 2];
__device__ float    d_eedge[TT * EE * 2];           // e logits, then exp(e-max)
__device__ float    d_acc[(size_t)NN * HD];         // sum over etypes of segment sums
__device__ float    d_hbuf[2 * (size_t)NN * DD];    // layer activations ping-pong

// monotonic float<->uint encoding for atomicMax over signed floats
__device__ __forceinline__ unsigned encf(float f) {
    unsigned u = __float_as_uint(f);
    return (u & 0x80000000u) ? ~u : (u | 0x80000000u);
}
__device__ __forceinline__ float decf(unsigned u) {
    return (u & 0x80000000u) ? __uint_as_float(u & 0x7FFFFFFFu) : __uint_as_float(~u);
}

// -------- feat = h @ W  (+ el/er reductions), one block per (node), gridDim.y = etype
template <int K>
__global__ void gemm_feat_kernel(const float* __restrict__ xin,
                                 const float* __restrict__ W,    // (T,K,HD)
                                 const float* __restrict__ al,   // (T,HD)
                                 const float* __restrict__ ar) { // (T,HD)
    int n = blockIdx.x;
    int t = blockIdx.y;
    int tid = threadIdx.x; // 0..127 => hd index
    __shared__ float xs[K];
    if (tid < K) xs[tid] = xin[(size_t)n * K + tid];
    __syncthreads();
    const float* Wt = W + (size_t)t * K * HD;
    float v = 0.f;
#pragma unroll
    for (int k = 0; k < K; k++) v = fmaf(xs[k], Wt[k * HD + tid], v);
    d_feat[((size_t)t * NN + n) * HD + tid] = v;

    float pl = v * al[t * HD + tid];
    float pr = v * ar[t * HD + tid];
#pragma unroll
    for (int o = 16; o > 0; o >>= 1) {
        pl += __shfl_down_sync(0xffffffffu, pl, o);
        pr += __shfl_down_sync(0xffffffffu, pr, o);
    }
    __shared__ float sl[4], sr[4];
    if ((tid & 31) == 0) { sl[tid >> 5] = pl; sr[tid >> 5] = pr; }
    __syncthreads();
    if (tid == 0) {
        int base = (t * NN + n) * 2;
        d_el[base + 0] = sl[0] + sl[1];
        d_el[base + 1] = sl[2] + sl[3];
        d_er[base + 0] = sr[0] + sr[1];
        d_er[base + 1] = sr[2] + sr[3];
    }
}

__global__ void clear_bufs_kernel() {
    int i = blockIdx.x * blockDim.x + threadIdx.x;
    int stride = gridDim.x * blockDim.x;
    for (int j = i; j < TT * NN * 2; j += stride) {
        d_emax[j] = 0u;       // below encf(any real value we produce)
        d_denom[j] = 0.f;
    }
    for (size_t j = i; j < (size_t)NN * HD; j += stride) d_acc[j] = 0.f;
}

// e = leaky_relu(el[src] + er[dst]); segment max over dst
__global__ void edge_logits_kernel(const int* __restrict__ edges) {
    int i = blockIdx.x * blockDim.x + threadIdx.x;
    if (i >= TT * EE) return;
    int t = i / EE, e = i - t * EE;
    const int* eb = edges + (size_t)t * 2 * EE;
    int s = eb[e], d = eb[EE + e];
    float2 elv = *(const float2*)&d_el[(t * NN + s) * 2];
    float2 erv = *(const float2*)&d_er[(t * NN + d) * 2];
    float e0 = elv.x + erv.x; e0 = e0 > 0.f ? e0 : 0.2f * e0;
    float e1 = elv.y + erv.y; e1 = e1 > 0.f ? e1 : 0.2f * e1;
    d_eedge[i * 2 + 0] = e0;
    d_eedge[i * 2 + 1] = e1;
    atomicMax(&d_emax[(t * NN + d) * 2 + 0], encf(e0));
    atomicMax(&d_emax[(t * NN + d) * 2 + 1], encf(e1));
}

// ex = exp(e - max); segment sum over dst
__global__ void edge_exp_kernel(const int* __restrict__ edges) {
    int i = blockIdx.x * blockDim.x + threadIdx.x;
    if (i >= TT * EE) return;
    int t = i / EE, e = i - t * EE;
    int d = edges[(size_t)t * 2 * EE + EE + e];
    int base = (t * NN + d) * 2;
    float m0 = decf(d_emax[base + 0]);
    float m1 = decf(d_emax[base + 1]);
    float ex0 = expf(d_eedge[i * 2 + 0] - m0);
    float ex1 = expf(d_eedge[i * 2 + 1] - m1);
    d_eedge[i * 2 + 0] = ex0;
    d_eedge[i * 2 + 1] = ex1;
    atomicAdd(&d_denom[base + 0], ex0);
    atomicAdd(&d_denom[base + 1], ex1);
}

// one warp per (etype, edge): acc[dst] += feat[src] * alpha   (float4 vector REDs)
__global__ void message_kernel(const int* __restrict__ edges) {
    int warp = (blockIdx.x * blockDim.x + threadIdx.x) >> 5;
    int lane = threadIdx.x & 31;
    if (warp >= TT * EE) return;
    int t = warp / EE, e = warp - t * EE;
    const int* eb = edges + (size_t)t * 2 * EE;
    int s = eb[e], d = eb[EE + e];
    float2 exv = *(const float2*)&d_eedge[warp * 2];
    float2 den = *(const float2*)&d_denom[(t * NN + d) * 2];
    float a0 = exv.x / den.x;
    float a1 = exv.y / den.y;
    float alpha = (lane < 16) ? a0 : a1;  // floats [0,64) = head 0, [64,128) = head 1
    const float4* fsrc = (const float4*)&d_feat[((size_t)t * NN + s) * HD];
    float4 f = fsrc[lane];
    f.x *= alpha; f.y *= alpha; f.z *= alpha; f.w *= alpha;
    atomicAdd(((float4*)&d_acc[(size_t)d * HD]) + lane, f);
}

// relu -> L2-normalize across heads -> mean over heads
__global__ void post_kernel(const float* __restrict__ b, float* __restrict__ hout) {
    int i = blockIdx.x * blockDim.x + threadIdx.x;
    if (i >= NN * DD) return;
    int n = i / DD, dd = i - n * DD;
    float bm0 = 0.f, bm1 = 0.f;
#pragma unroll
    for (int t = 0; t < TT; t++) {
        bm0 += b[t * HD + dd];
        bm1 += b[t * HD + DD + dd];
    }
    bm0 *= 0.25f; bm1 *= 0.25f;
    float v0 = d_acc[(size_t)n * HD + dd]       * 0.25f + bm0;
    float v1 = d_acc[(size_t)n * HD + DD + dd]  * 0.25f + bm1;
    v0 = fmaxf(v0, 0.f);
    v1 = fmaxf(v1, 0.f);
    float nrm = sqrtf(v0 * v0 + v1 * v1);
    float inv = 1.f / fmaxf(nrm, 1e-12f);
    hout[(size_t)n * DD + dd] = 0.5f * (v0 + v1) * inv;
}

__global__ void zero_out_kernel(float* out) {
    if (threadIdx.x < DD) out[threadIdx.x] = 0.f;
}

// final: mean over heads then mean over nodes
__global__ void final_reduce_kernel(const float* __restrict__ b, float* __restrict__ out) {
    int dd  = threadIdx.x & 63;
    int grp = threadIdx.x >> 6;   // 0..3
    float bm0 = 0.f, bm1 = 0.f;
#pragma unroll
    for (int t = 0; t < TT; t++) {
        bm0 += b[t * HD + dd];
        bm1 += b[t * HD + DD + dd];
    }
    bm0 *= 0.25f; bm1 *= 0.25f;
    float acc = 0.f;
    for (int n = blockIdx.x * 4 + grp; n < NN; n += gridDim.x * 4) {
        float v0 = d_acc[(size_t)n * HD + dd]      * 0.25f + bm0;
        float v1 = d_acc[(size_t)n * HD + DD + dd] * 0.25f + bm1;
        acc += 0.5f * (v0 + v1);
    }
    __shared__ float sm[256];
    sm[threadIdx.x] = acc;
    __syncthreads();
    if (grp == 0) {
        float s = sm[dd] + sm[64 + dd] + sm[128 + dd] + sm[192 + dd];
        atomicAdd(&out[dd], s * (1.0f / NN));
    }
}

extern "C" void kernel_launch(void* const* d_in, const int* in_sizes, int n_in,
                              void* d_out, int out_size) {
    const float* x   = (const float*)d_in[0];
    const int* edges = (const int*)  d_in[1];
    const float* W0  = (const float*)d_in[2];
    const float* al0 = (const float*)d_in[3];
    const float* ar0 = (const float*)d_in[4];
    const float* b0  = (const float*)d_in[5];
    const float* W1  = (const float*)d_in[6];
    const float* al1 = (const float*)d_in[7];
    const float* ar1 = (const float*)d_in[8];
    const float* b1  = (const float*)d_in[9];
    const float* W2  = (const float*)d_in[10];
    const float* al2 = (const float*)d_in[11];
    const float* ar2 = (const float*)d_in[12];
    const float* b2  = (const float*)d_in[13];
    float* out = (float*)d_out;

    void* hptr = nullptr;
    cudaGetSymbolAddress(&hptr, d_hbuf);
    float* h1 = (float*)hptr;
    float* h2 = h1 + (size_t)NN * DD;

    dim3 gblk(NN, TT);
    const int ET = TT * EE;
    const int eg = (ET + 255) / 256;
    const int mg = (ET * 32 + 255) / 256;
    const int pg = (NN * DD + 255) / 256;

    // ---- layer 0 ----
    gemm_feat_kernel<23><<<gblk, 128>>>(x, W0, al0, ar0);
    clear_bufs_kernel<<<1024, 256>>>();
    edge_logits_kernel<<<eg, 256>>>(edges);
    edge_exp_kernel<<<eg, 256>>>(edges);
    message_kernel<<<mg, 256>>>(edges);
    post_kernel<<<pg, 256>>>(b0, h1);

    // ---- layer 1 ----
    gemm_feat_kernel<64><<<gblk, 128>>>(h1, W1, al1, ar1);
    clear_bufs_kernel<<<1024, 256>>>();
    edge_logits_kernel<<<eg, 256>>>(edges);
    edge_exp_kernel<<<eg, 256>>>(edges);
    message_kernel<<<mg, 256>>>(edges);
    post_kernel<<<pg, 256>>>(b1, h2);

    // ---- layer 2 ----
    gemm_feat_kernel<64><<<gblk, 128>>>(h2, W2, al2, ar2);
    clear_bufs_kernel<<<1024, 256>>>();
    edge_logits_kernel<<<eg, 256>>>(edges);
    edge_exp_kernel<<<eg, 256>>>(edges);
    message_kernel<<<mg, 256>>>(edges);

    zero_out_kernel<<<1, 64>>>(out);
    final_reduce_kernel<<<512, 256>>>(b2, out);
}

// round 3
// speedup vs baseline: 1.9691x; 1.9691x over previous
#include <cuda_runtime.h>
#include <cuda_bf16.h>

#define NN 50000
#define EE 250000
#define TT 4
#define ROWS (TT*NN)
#define ETOT (TT*EE)
#define CHUNK 1024
#define NBLK ((ROWS + CHUNK - 1) / CHUNK)   // 196

// ---------------- scratch (static device globals) ----------------
__device__ float d_el[ROWS * 2];
__device__ float d_er[ROWS * 2];
__device__ float d_wal[TT * 2 * 64];
__device__ float d_war[TT * 2 * 64];
__device__ float d_agg[(size_t)ROWS * 128];     // (t,n, head, K) max 102.4MB
__device__ float d_acc[(size_t)NN * 128];
__device__ float d_hbuf[2 * (size_t)NN * 64];
__device__ int   d_deg[ROWS];
__device__ int   d_rowptr[ROWS + 1];
__device__ int   d_cursor[ROWS];
__device__ int   d_csrc[ETOT];
__device__ int   d_bsum[256];

// ---------------- f32x2 packed helpers ----------------
__device__ __forceinline__ unsigned long long f32x2_bcast(float x) {
    unsigned long long r;
    asm("mov.b64 %0, {%1, %1};" : "=l"(r) : "f"(x));
    return r;
}
__device__ __forceinline__ float2 f32x2_unpack(unsigned long long v) {
    float2 f;
    asm("mov.b64 {%0, %1}, %2;" : "=f"(f.x), "=f"(f.y) : "l"(v));
    return f;
}
#define FMA2(d, a, b, c) \
    asm("fma.rn.f32x2 %0, %1, %2, %3;" : "=l"(d) : "l"(a), "l"(b), "l"(c))

// ================= CSR build (edges constant across layers) =================
__global__ void zero_deg_kernel() {
    int i = blockIdx.x * blockDim.x + threadIdx.x;
    if (i < ROWS) d_deg[i] = 0;
}

__global__ void hist_kernel(const int* __restrict__ edges) {
    int i = blockIdx.x * blockDim.x + threadIdx.x;
    if (i >= ETOT) return;
    int t = i / EE, e = i - t * EE;
    int d = edges[(size_t)t * 2 * EE + EE + e];
    atomicAdd(&d_deg[t * NN + d], 1);
}

__global__ void scan_k1() {
    __shared__ int sm[256];
    int b = blockIdx.x, tid = threadIdx.x;
    int s = 0;
#pragma unroll
    for (int i = 0; i < 4; i++) {
        int idx = b * CHUNK + tid + 256 * i;
        if (idx < ROWS) s += d_deg[idx];
    }
    sm[tid] = s;
    __syncthreads();
    for (int o = 128; o > 0; o >>= 1) {
        if (tid < o) sm[tid] += sm[tid + o];
        __syncthreads();
    }
    if (tid == 0) d_bsum[b] = sm[0];
}

__global__ void scan_k2() {
    __shared__ int sm[256];
    int tid = threadIdx.x;
    int own = (tid < NBLK) ? d_bsum[tid] : 0;
    sm[tid] = own;
    __syncthreads();
    for (int o = 1; o < 256; o <<= 1) {
        int add = (tid >= o) ? sm[tid - o] : 0;
        __syncthreads();
        sm[tid] += add;
        __syncthreads();
    }
    if (tid < NBLK) d_bsum[tid] = sm[tid] - own;   // exclusive
}

__global__ void scan_k3() {
    __shared__ int sm[256];
    int b = blockIdx.x, tid = threadIdx.x;
    int base = b * CHUNK + tid * 4;
    int v[4], p[4], s = 0;
#pragma unroll
    for (int i = 0; i < 4; i++) {
        int idx = base + i;
        v[i] = (idx < ROWS) ? d_deg[idx] : 0;
        p[i] = s;
        s += v[i];
    }
    sm[tid] = s;
    __syncthreads();
    for (int o = 1; o < 256; o <<= 1) {
        int add = (tid >= o) ? sm[tid - o] : 0;
        __syncthreads();
        sm[tid] += add;
        __syncthreads();
    }
    int off = d_bsum[b] + (tid ? sm[tid - 1] : 0);
#pragma unroll
    for (int i = 0; i < 4; i++) {
        int idx = base + i;
        if (idx < ROWS) {
            d_rowptr[idx] = off + p[i];
            d_cursor[idx] = off + p[i];
        }
    }
    if (b == 0 && tid == 0) d_rowptr[ROWS] = ETOT;
}

__global__ void scatter_kernel(const int* __restrict__ edges) {
    int i = blockIdx.x * blockDim.x + threadIdx.x;
    if (i >= ETOT) return;
    int t = i / EE, e = i - t * EE;
    int s = edges[(size_t)t * 2 * EE + e];
    int d = edges[(size_t)t * 2 * EE + EE + e];
    int pos = atomicAdd(&d_cursor[t * NN + d], 1);
    d_csrc[pos] = s;
}

// ================= per-layer kernels =================
// wal[t,h,k] = sum_j W[t,k, h*64+j] * al[t,h,j]   (stored with stride 64 in k)
__global__ void walwar_kernel(const float* __restrict__ W,
                              const float* __restrict__ al,
                              const float* __restrict__ ar, int K) {
    int tid = threadIdx.x;
    if (tid >= TT * 2 * K) return;
    int t = tid / (2 * K);
    int rem = tid - t * 2 * K;
    int hh = rem / K;
    int k = rem - hh * K;
    float sl = 0.f, sr = 0.f;
    const float* Wr = W + ((size_t)(t * K + k)) * 128 + hh * 64;
    const float* alr = al + (t * 2 + hh) * 64;
    const float* arr = ar + (t * 2 + hh) * 64;
#pragma unroll
    for (int j = 0; j < 64; j++) {
        float w = Wr[j];
        sl = fmaf(w, alr[j], sl);
        sr = fmaf(w, arr[j], sr);
    }
    d_wal[(t * 2 + hh) * 64 + k] = sl;
    d_war[(t * 2 + hh) * 64 + k] = sr;
}

// el[(t*NN+n)*2+hh] = sum_k h[n,k] * wal[t,hh,k] ; one warp per node
template <int K>
__global__ void eler_kernel(const float* __restrict__ h) {
    __shared__ float swal[512], swar[512];
    int tid = threadIdx.x;
    if (tid < 256) {
        swal[tid] = d_wal[tid];       swal[tid + 256] = d_wal[tid + 256];
        swar[tid] = d_war[tid];       swar[tid + 256] = d_war[tid + 256];
    }
    __syncthreads();
    int lane = tid & 31;
    int n = (blockIdx.x * blockDim.x + tid) >> 5;
    if (n >= NN) return;
    float h0 = (lane < K) ? h[(size_t)n * K + lane] : 0.f;
    float h1 = (K > 32 && lane + 32 < K) ? h[(size_t)n * K + lane + 32] : 0.f;
#pragma unroll
    for (int t = 0; t < TT; t++) {
#pragma unroll
        for (int hh = 0; hh < 2; hh++) {
            int base = (t * 2 + hh) * 64;
            float pl = h0 * swal[base + lane];
            float pr = h0 * swar[base + lane];
            if (K > 32) {
                pl = fmaf(h1, swal[base + lane + 32], pl);
                pr = fmaf(h1, swar[base + lane + 32], pr);
            }
#pragma unroll
            for (int o = 16; o > 0; o >>= 1) {
                pl += __shfl_down_sync(0xffffffffu, pl, o);
                pr += __shfl_down_sync(0xffffffffu, pr, o);
            }
            if (lane == 0) {
                d_el[((size_t)t * NN + n) * 2 + hh] = pl;
                d_er[((size_t)t * NN + n) * 2 + hh] = pr;
            }
        }
    }
}

__device__ __forceinline__ float lrelu(float x) { return x > 0.f ? x : 0.2f * x; }

// one warp per (t,d) segment: softmax over in-edges + agg = sum alpha*h[src]
template <int K>
__global__ void segment_kernel(const float* __restrict__ h) {
    int tid = threadIdx.x;
    int lane = tid & 31;
    int row = (blockIdx.x * blockDim.x + tid) >> 5;   // t*NN + d
    if (row >= ROWS) return;
    int t = row / NN;
    int beg = d_rowptr[row], end = d_rowptr[row + 1];
    float2 er2 = *(const float2*)&d_er[(size_t)row * 2];

    // pass 1: max
    float m0 = -1e30f, m1 = -1e30f;
    for (int j = beg + lane; j < end; j += 32) {
        int s = d_csrc[j];
        float2 el2 = *(const float2*)&d_el[((size_t)t * NN + s) * 2];
        m0 = fmaxf(m0, lrelu(el2.x + er2.x));
        m1 = fmaxf(m1, lrelu(el2.y + er2.y));
    }
#pragma unroll
    for (int o = 16; o > 0; o >>= 1) {
        m0 = fmaxf(m0, __shfl_xor_sync(0xffffffffu, m0, o));
        m1 = fmaxf(m1, __shfl_xor_sync(0xffffffffu, m1, o));
    }
    // pass 2: denom
    float s0 = 0.f, s1 = 0.f;
    for (int j = beg + lane; j < end; j += 32) {
        int s = d_csrc[j];
        float2 el2 = *(const float2*)&d_el[((size_t)t * NN + s) * 2];
        s0 += expf(lrelu(el2.x + er2.x) - m0);
        s1 += expf(lrelu(el2.y + er2.y) - m1);
    }
#pragma unroll
    for (int o = 16; o > 0; o >>= 1) {
        s0 += __shfl_xor_sync(0xffffffffu, s0, o);
        s1 += __shfl_xor_sync(0xffffffffu, s1, o);
    }
    float inv0 = (end > beg) ? 1.f / s0 : 0.f;
    float inv1 = (end > beg) ? 1.f / s1 : 0.f;

    // pass 3: aggregate
    float2 acc0 = make_float2(0.f, 0.f), acc1 = make_float2(0.f, 0.f);
    float accs0 = 0.f, accs1 = 0.f;     // scalar path (K<=32)
    for (int jb = beg; jb < end; jb += 32) {
        int j = jb + lane;
        int sreg = 0;
        float ex0 = 0.f, ex1 = 0.f;
        if (j < end) {
            sreg = d_csrc[j];
            float2 el2 = *(const float2*)&d_el[((size_t)t * NN + sreg) * 2];
            ex0 = expf(lrelu(el2.x + er2.x) - m0);
            ex1 = expf(lrelu(el2.y + er2.y) - m1);
        }
        int cnt = min(32, end - jb);
        for (int jj = 0; jj < cnt; jj++) {
            int ss = __shfl_sync(0xffffffffu, sreg, jj);
            float a0 = __shfl_sync(0xffffffffu, ex0, jj) * inv0;
            float a1 = __shfl_sync(0xffffffffu, ex1, jj) * inv1;
            if (K == 64) {
                float2 hv = *(const float2*)&h[(size_t)ss * 64 + 2 * lane];
                acc0.x = fmaf(a0, hv.x, acc0.x);
                acc0.y = fmaf(a0, hv.y, acc0.y);
                acc1.x = fmaf(a1, hv.x, acc1.x);
                acc1.y = fmaf(a1, hv.y, acc1.y);
            } else {
                float hv = (lane < K) ? h[(size_t)ss * K + lane] : 0.f;
                accs0 = fmaf(a0, hv, accs0);
                accs1 = fmaf(a1, hv, accs1);
            }
        }
    }
    size_t base = (size_t)row * 2 * K;
    if (K == 64) {
        *(float2*)&d_agg[base + 2 * lane] = acc0;
        *(float2*)&d_agg[base + K + 2 * lane] = acc1;
    } else {
        if (lane < K) {
            d_agg[base + lane] = accs0;
            d_agg[base + K + lane] = accs1;
        }
    }
}

// acc[n, col] = sum_t sum_k agg[t,n,head(col),k] * W[t,k,col]
// block: 256 threads, 32-node x 128-col tile; packed f32x2 FMA
template <int K>
__global__ void out_gemm_kernel(const float* __restrict__ W) {
    __shared__ __align__(16) float Ws[K * 128];
    __shared__ __align__(16) float As[32 * 2 * K];
    int tid = threadIdx.x;
    int cp = tid & 63;          // column pair: cols 2cp, 2cp+1
    int g = tid >> 6;           // node group: nodes g*8 .. g*8+7
    int head = cp >> 5;
    int nbase = blockIdx.x * 32;
    int nvalid = min(32, NN - nbase);

    unsigned long long acc[8];
#pragma unroll
    for (int i = 0; i < 8; i++) acc[i] = 0ull;

    for (int t = 0; t < TT; t++) {
        const float* Wg = W + (size_t)t * K * 128;
        for (int i = tid; i < K * 128 / 4; i += 256)
            ((float4*)Ws)[i] = ((const float4*)Wg)[i];
        const float* Ag = d_agg + ((size_t)t * NN + nbase) * 2 * K;
        int tot2 = nvalid * K;              // (nvalid*2K)/2 float2 elements
        for (int i = tid; i < tot2; i += 256)
            ((float2*)As)[i] = ((const float2*)Ag)[i];
        __syncthreads();

        const float* arow = As + (g * 8) * 2 * K + head * K;
        for (int k = 0; k < K; k++) {
            unsigned long long w = *(const unsigned long long*)&Ws[k * 128 + 2 * cp];
#pragma unroll
            for (int i = 0; i < 8; i++) {
                unsigned long long a = f32x2_bcast(arow[i * 2 * K + k]);
                FMA2(acc[i], a, w, acc[i]);
            }
        }
        __syncthreads();
    }
#pragma unroll
    for (int i = 0; i < 8; i++) {
        int n = nbase + g * 8 + i;
        if (n < NN) {
            float2 v = f32x2_unpack(acc[i]);
            *(float2*)&d_acc[(size_t)n * 128 + 2 * cp] = v;
        }
    }
}

// ================= post / final (unchanged semantics) =================
__global__ void post_kernel(const float* __restrict__ b, float* __restrict__ hout) {
    int i = blockIdx.x * blockDim.x + threadIdx.x;
    if (i >= NN * 64) return;
    int n = i / 64, dd = i - n * 64;
    float bm0 = 0.f, bm1 = 0.f;
#pragma unroll
    for (int t = 0; t < TT; t++) {
        bm0 += b[t * 128 + dd];
        bm1 += b[t * 128 + 64 + dd];
    }
    bm0 *= 0.25f; bm1 *= 0.25f;
    float v0 = d_acc[(size_t)n * 128 + dd] * 0.25f + bm0;
    float v1 = d_acc[(size_t)n * 128 + 64 + dd] * 0.25f + bm1;
    v0 = fmaxf(v0, 0.f);
    v1 = fmaxf(v1, 0.f);
    float nrm = sqrtf(v0 * v0 + v1 * v1);
    float inv = 1.f / fmaxf(nrm, 1e-12f);
    hout[(size_t)n * 64 + dd] = 0.5f * (v0 + v1) * inv;
}

__global__ void zero_out_kernel(float* out) {
    if (threadIdx.x < 64) out[threadIdx.x] = 0.f;
}

__global__ void final_reduce_kernel(const float* __restrict__ b, float* __restrict__ out) {
    int dd = threadIdx.x & 63;
    int grp = threadIdx.x >> 6;
    float bm0 = 0.f, bm1 = 0.f;
#pragma unroll
    for (int t = 0; t < TT; t++) {
        bm0 += b[t * 128 + dd];
        bm1 += b[t * 128 + 64 + dd];
    }
    bm0 *= 0.25f; bm1 *= 0.25f;
    float acc = 0.f;
    for (int n = blockIdx.x * 4 + grp; n < NN; n += gridDim.x * 4) {
        float v0 = d_acc[(size_t)n * 128 + dd] * 0.25f + bm0;
        float v1 = d_acc[(size_t)n * 128 + 64 + dd] * 0.25f + bm1;
        acc += 0.5f * (v0 + v1);
    }
    __shared__ float sm[256];
    sm[threadIdx.x] = acc;
    __syncthreads();
    if (grp == 0) {
        float s = sm[dd] + sm[64 + dd] + sm[128 + dd] + sm[192 + dd];
        atomicAdd(&out[dd], s * (1.0f / NN));
    }
}

// ================= driver =================
extern "C" void kernel_launch(void* const* d_in, const int* in_sizes, int n_in,
                              void* d_out, int out_size) {
    const float* x   = (const float*)d_in[0];
    const int* edges = (const int*)  d_in[1];
    const float* W0  = (const float*)d_in[2];
    const float* al0 = (const float*)d_in[3];
    const float* ar0 = (const float*)d_in[4];
    const float* b0  = (const float*)d_in[5];
    const float* W1  = (const float*)d_in[6];
    const float* al1 = (const float*)d_in[7];
    const float* ar1 = (const float*)d_in[8];
    const float* b1  = (const float*)d_in[9];
    const float* W2  = (const float*)d_in[10];
    const float* al2 = (const float*)d_in[11];
    const float* ar2 = (const float*)d_in[12];
    const float* b2  = (const float*)d_in[13];
    float* out = (float*)d_out;

    void* hptr = nullptr;
    cudaGetSymbolAddress(&hptr, d_hbuf);
    float* h1 = (float*)hptr;
    float* h2 = h1 + (size_t)NN * 64;

    const int eg = (ETOT + 255) / 256;
    const int ng = (NN * 32 + 255) / 256;       // eler: one full warp per node (FIXED)
    const int sg = (ROWS * 32 + 255) / 256;     // segment: warp per row
    const int gg = (NN + 31) / 32;              // out gemm
    const int pg = (NN * 64 + 255) / 256;

    // ---- CSR build (edges fixed across layers) ----
    zero_deg_kernel<<<(ROWS + 255) / 256, 256>>>();
    hist_kernel<<<eg, 256>>>(edges);
    scan_k1<<<NBLK, 256>>>();
    scan_k2<<<1, 256>>>();
    scan_k3<<<NBLK, 256>>>();
    scatter_kernel<<<eg, 256>>>(edges);

    // ---- layer 0 (K=23) ----
    walwar_kernel<<<1, TT * 2 * 23>>>(W0, al0, ar0, 23);
    eler_kernel<23><<<ng, 256>>>(x);
    segment_kernel<23><<<sg, 256>>>(x);
    out_gemm_kernel<23><<<gg, 256>>>(W0);
    post_kernel<<<pg, 256>>>(b0, h1);

    // ---- layer 1 (K=64) ----
    walwar_kernel<<<1, TT * 2 * 64>>>(W1, al1, ar1, 64);
    eler_kernel<64><<<ng, 256>>>(h1);
    segment_kernel<64><<<sg, 256>>>(h1);
    out_gemm_kernel<64><<<gg, 256>>>(W1);
    post_kernel<<<pg, 256>>>(b1, h2);

    // ---- layer 2 (K=64) ----
    walwar_kernel<<<1, TT * 2 * 64>>>(W2, al2, ar2, 64);
    eler_kernel<64><<<ng, 256>>>(h2);
    segment_kernel<64><<<sg, 256>>>(h2);
    out_gemm_kernel<64><<<gg, 256>>>(W2);

    zero_out_kernel<<<1, 64>>>(out);
    final_reduce_kernel<<<512, 256>>>(b2, out);
}

// round 4
// speedup vs baseline: 2.2995x; 1.1678x over previous
#include <cuda_runtime.h>
#include <cuda_bf16.h>

#define NN 50000
#define EE 250000
#define TT 4
#define ROWS (TT*NN)
#define ETOT (TT*EE)
#define CHUNK 1024
#define NBLK ((ROWS + CHUNK - 1) / CHUNK)   // 196

// ---------------- scratch (static device globals) ----------------
__device__ float  d_el[ROWS * 2];
__device__ float  d_er[ROWS * 2];
__device__ float  d_wal[TT * 2 * 64];
__device__ float  d_war[TT * 2 * 64];
__device__ float  d_agg[(size_t)ROWS * 128];     // (t,n, head, K) max 102.4MB
__device__ float  d_acc[(size_t)NN * 128];
__device__ float  d_hbuf[2 * (size_t)NN * 64];
__device__ float2 d_ew2[ETOT];                   // exp(edge logits), CSR order
__device__ float  d_msum[TT * 128];              // layer-2 node-mean of agg
__device__ int    d_deg[ROWS];
__device__ int    d_rowptr[ROWS + 1];
__device__ int    d_cursor[ROWS];
__device__ int    d_csrc[ETOT];
__device__ int    d_epos[ETOT];                  // edge -> CSR slot
__device__ int    d_bsum[256];

// ---------------- f32x2 packed helpers ----------------
__device__ __forceinline__ unsigned long long f32x2_bcast(float x) {
    unsigned long long r;
    asm("mov.b64 %0, {%1, %1};" : "=l"(r) : "f"(x));
    return r;
}
__device__ __forceinline__ float2 f32x2_unpack(unsigned long long v) {
    float2 f;
    asm("mov.b64 {%0, %1}, %2;" : "=f"(f.x), "=f"(f.y) : "l"(v));
    return f;
}
#define FMA2(d, a, b, c) \
    asm("fma.rn.f32x2 %0, %1, %2, %3;" : "=l"(d) : "l"(a), "l"(b), "l"(c))

__device__ __forceinline__ float lrelu(float x) { return x > 0.f ? x : 0.2f * x; }

// ================= CSR build (edges constant across layers) =================
__global__ void zero_deg_kernel() {
    int i = blockIdx.x * blockDim.x + threadIdx.x;
    if (i < ROWS) d_deg[i] = 0;
    if (i < TT * 128) d_msum[i] = 0.f;
}

__global__ void hist_kernel(const int* __restrict__ edges) {
    int i = blockIdx.x * blockDim.x + threadIdx.x;
    if (i >= ETOT) return;
    int t = i / EE, e = i - t * EE;
    int d = edges[(size_t)t * 2 * EE + EE + e];
    atomicAdd(&d_deg[t * NN + d], 1);
}

__global__ void scan_k1() {
    __shared__ int sm[256];
    int b = blockIdx.x, tid = threadIdx.x;
    int s = 0;
#pragma unroll
    for (int i = 0; i < 4; i++) {
        int idx = b * CHUNK + tid + 256 * i;
        if (idx < ROWS) s += d_deg[idx];
    }
    sm[tid] = s;
    __syncthreads();
    for (int o = 128; o > 0; o >>= 1) {
        if (tid < o) sm[tid] += sm[tid + o];
        __syncthreads();
    }
    if (tid == 0) d_bsum[b] = sm[0];
}

__global__ void scan_k2() {
    __shared__ int sm[256];
    int tid = threadIdx.x;
    int own = (tid < NBLK) ? d_bsum[tid] : 0;
    sm[tid] = own;
    __syncthreads();
    for (int o = 1; o < 256; o <<= 1) {
        int add = (tid >= o) ? sm[tid - o] : 0;
        __syncthreads();
        sm[tid] += add;
        __syncthreads();
    }
    if (tid < NBLK) d_bsum[tid] = sm[tid] - own;   // exclusive
}

__global__ void scan_k3() {
    __shared__ int sm[256];
    int b = blockIdx.x, tid = threadIdx.x;
    int base = b * CHUNK + tid * 4;
    int v[4], p[4], s = 0;
#pragma unroll
    for (int i = 0; i < 4; i++) {
        int idx = base + i;
        v[i] = (idx < ROWS) ? d_deg[idx] : 0;
        p[i] = s;
        s += v[i];
    }
    sm[tid] = s;
    __syncthreads();
    for (int o = 1; o < 256; o <<= 1) {
        int add = (tid >= o) ? sm[tid - o] : 0;
        __syncthreads();
        sm[tid] += add;
        __syncthreads();
    }
    int off = d_bsum[b] + (tid ? sm[tid - 1] : 0);
#pragma unroll
    for (int i = 0; i < 4; i++) {
        int idx = base + i;
        if (idx < ROWS) {
            d_rowptr[idx] = off + p[i];
            d_cursor[idx] = off + p[i];
        }
    }
    if (b == 0 && tid == 0) d_rowptr[ROWS] = ETOT;
}

__global__ void scatter_kernel(const int* __restrict__ edges) {
    int i = blockIdx.x * blockDim.x + threadIdx.x;
    if (i >= ETOT) return;
    int t = i / EE, e = i - t * EE;
    int s = edges[(size_t)t * 2 * EE + e];
    int d = edges[(size_t)t * 2 * EE + EE + e];
    int pos = atomicAdd(&d_cursor[t * NN + d], 1);
    d_csrc[pos] = s;
    d_epos[i] = pos;
}

// ================= per-layer kernels =================
// wal[t,h,k] = sum_j W[t,k, h*64+j] * al[t,h,j]
__global__ void walwar_kernel(const float* __restrict__ W,
                              const float* __restrict__ al,
                              const float* __restrict__ ar, int K) {
    int tid = threadIdx.x;
    if (tid >= TT * 2 * K) return;
    int t = tid / (2 * K);
    int rem = tid - t * 2 * K;
    int hh = rem / K;
    int k = rem - hh * K;
    float sl = 0.f, sr = 0.f;
    const float* Wr = W + ((size_t)(t * K + k)) * 128 + hh * 64;
    const float* alr = al + (t * 2 + hh) * 64;
    const float* arr = ar + (t * 2 + hh) * 64;
#pragma unroll
    for (int j = 0; j < 64; j++) {
        float w = Wr[j];
        sl = fmaf(w, alr[j], sl);
        sr = fmaf(w, arr[j], sr);
    }
    d_wal[(t * 2 + hh) * 64 + k] = sl;
    d_war[(t * 2 + hh) * 64 + k] = sr;
}

// el/er per node; one warp per node
template <int K>
__global__ void eler_kernel(const float* __restrict__ h) {
    __shared__ float swal[512], swar[512];
    int tid = threadIdx.x;
    if (tid < 256) {
        swal[tid] = d_wal[tid];       swal[tid + 256] = d_wal[tid + 256];
        swar[tid] = d_war[tid];       swar[tid + 256] = d_war[tid + 256];
    }
    __syncthreads();
    int lane = tid & 31;
    int n = (blockIdx.x * blockDim.x + tid) >> 5;
    if (n >= NN) return;
    float h0 = (lane < K) ? h[(size_t)n * K + lane] : 0.f;
    float h1 = (K > 32 && lane + 32 < K) ? h[(size_t)n * K + lane + 32] : 0.f;
#pragma unroll
    for (int t = 0; t < TT; t++) {
#pragma unroll
        for (int hh = 0; hh < 2; hh++) {
            int base = (t * 2 + hh) * 64;
            float pl = h0 * swal[base + lane];
            float pr = h0 * swar[base + lane];
            if (K > 32) {
                pl = fmaf(h1, swal[base + lane + 32], pl);
                pr = fmaf(h1, swar[base + lane + 32], pr);
            }
#pragma unroll
            for (int o = 16; o > 0; o >>= 1) {
                pl += __shfl_down_sync(0xffffffffu, pl, o);
                pr += __shfl_down_sync(0xffffffffu, pr, o);
            }
            if (lane == 0) {
                d_el[((size_t)t * NN + n) * 2 + hh] = pl;
                d_er[((size_t)t * NN + n) * 2 + hh] = pr;
            }
        }
    }
}

// edge-parallel: ew = exp(lrelu(el[src]+er[dst])) written to CSR slot.
// No max subtraction: logits are O(0.1) here, softmax is shift-invariant.
__global__ void edgeexp_kernel(const int* __restrict__ edges) {
    int i = blockIdx.x * blockDim.x + threadIdx.x;
    if (i >= ETOT) return;
    int t = i / EE, e = i - t * EE;
    int s = edges[(size_t)t * 2 * EE + e];
    int d = edges[(size_t)t * 2 * EE + EE + e];
    float2 el2 = *(const float2*)&d_el[((size_t)t * NN + s) * 2];
    float2 er2 = *(const float2*)&d_er[((size_t)t * NN + d) * 2];
    float w0 = __expf(lrelu(el2.x + er2.x));
    float w1 = __expf(lrelu(el2.y + er2.y));
    d_ew2[d_epos[i]] = make_float2(w0, w1);
}

// one warp per row: single pass, unnormalized accumulate + denom, scale at end
template <int K>
__global__ void segment2_kernel(const float* __restrict__ h) {
    int tid = threadIdx.x;
    int lane = tid & 31;
    int row = (blockIdx.x * blockDim.x + tid) >> 5;   // t*NN + d
    if (row >= ROWS) return;
    int beg = d_rowptr[row], end = d_rowptr[row + 1];

    float den0 = 0.f, den1 = 0.f;
    float2 a0 = make_float2(0.f, 0.f), a1 = make_float2(0.f, 0.f);
    float as0 = 0.f, as1 = 0.f;

    // software pipeline: prefetch next (ew, src, h) while consuming current
    float2 ew_c = make_float2(0.f, 0.f);
    float2 hv_c = make_float2(0.f, 0.f);
    float  hs_c = 0.f;
    if (beg < end) {
        ew_c = d_ew2[beg];
        int s = d_csrc[beg];
        if (K == 64) hv_c = ((const float2*)h)[(size_t)s * 32 + lane];
        else         hs_c = (lane < K) ? h[(size_t)s * K + lane] : 0.f;
    }
    for (int j = beg; j < end; j++) {
        float2 ew_n = make_float2(0.f, 0.f), hv_n = make_float2(0.f, 0.f);
        float hs_n = 0.f;
        if (j + 1 < end) {
            ew_n = d_ew2[j + 1];
            int sn = d_csrc[j + 1];
            if (K == 64) hv_n = ((const float2*)h)[(size_t)sn * 32 + lane];
            else         hs_n = (lane < K) ? h[(size_t)sn * K + lane] : 0.f;
        }
        den0 += ew_c.x;
        den1 += ew_c.y;
        if (K == 64) {
            a0.x = fmaf(ew_c.x, hv_c.x, a0.x);
            a0.y = fmaf(ew_c.x, hv_c.y, a0.y);
            a1.x = fmaf(ew_c.y, hv_c.x, a1.x);
            a1.y = fmaf(ew_c.y, hv_c.y, a1.y);
        } else {
            as0 = fmaf(ew_c.x, hs_c, as0);
            as1 = fmaf(ew_c.y, hs_c, as1);
        }
        ew_c = ew_n; hv_c = hv_n; hs_c = hs_n;
    }
    float inv0 = (end > beg) ? 1.f / den0 : 0.f;
    float inv1 = (end > beg) ? 1.f / den1 : 0.f;
    size_t base = (size_t)row * 2 * K;
    if (K == 64) {
        float2 o0 = make_float2(a0.x * inv0, a0.y * inv0);
        float2 o1 = make_float2(a1.x * inv1, a1.y * inv1);
        *(float2*)&d_agg[base + 2 * lane] = o0;
        *(float2*)&d_agg[base + K + 2 * lane] = o1;
    } else {
        if (lane < K) {
            d_agg[base + lane] = as0 * inv0;
            d_agg[base + K + lane] = as1 * inv1;
        }
    }
}

// acc[n, col] = sum_t sum_k agg[t,n,head(col),k] * W[t,k,col]
template <int K>
__global__ void out_gemm_kernel(const float* __restrict__ W) {
    __shared__ __align__(16) float Ws[K * 128];
    __shared__ __align__(16) float As[32 * 2 * K];
    int tid = threadIdx.x;
    int cp = tid & 63;          // column pair
    int g = tid >> 6;           // node group
    int head = cp >> 5;
    int nbase = blockIdx.x * 32;
    int nvalid = min(32, NN - nbase);

    unsigned long long acc[8];
#pragma unroll
    for (int i = 0; i < 8; i++) acc[i] = 0ull;

    for (int t = 0; t < TT; t++) {
        const float* Wg = W + (size_t)t * K * 128;
        for (int i = tid; i < K * 128 / 4; i += 256)
            ((float4*)Ws)[i] = ((const float4*)Wg)[i];
        const float* Ag = d_agg + ((size_t)t * NN + nbase) * 2 * K;
        int tot2 = nvalid * K;
        for (int i = tid; i < tot2; i += 256)
            ((float2*)As)[i] = ((const float2*)Ag)[i];
        __syncthreads();

        const float* arow = As + (g * 8) * 2 * K + head * K;
        for (int k = 0; k < K; k++) {
            unsigned long long w = *(const unsigned long long*)&Ws[k * 128 + 2 * cp];
#pragma unroll
            for (int i = 0; i < 8; i++) {
                unsigned long long a = f32x2_bcast(arow[i * 2 * K + k]);
                FMA2(acc[i], a, w, acc[i]);
            }
        }
        __syncthreads();
    }
#pragma unroll
    for (int i = 0; i < 8; i++) {
        int n = nbase + g * 8 + i;
        if (n < NN) {
            float2 v = f32x2_unpack(acc[i]);
            *(float2*)&d_acc[(size_t)n * 128 + 2 * cp] = v;
        }
    }
}

// ================= post =================
__global__ void post_kernel(const float* __restrict__ b, float* __restrict__ hout) {
    int i = blockIdx.x * blockDim.x + threadIdx.x;
    if (i >= NN * 64) return;
    int n = i / 64, dd = i - n * 64;
    float bm0 = 0.f, bm1 = 0.f;
#pragma unroll
    for (int t = 0; t < TT; t++) {
        bm0 += b[t * 128 + dd];
        bm1 += b[t * 128 + 64 + dd];
    }
    bm0 *= 0.25f; bm1 *= 0.25f;
    float v0 = d_acc[(size_t)n * 128 + dd] * 0.25f + bm0;
    float v1 = d_acc[(size_t)n * 128 + 64 + dd] * 0.25f + bm1;
    v0 = fmaxf(v0, 0.f);
    v1 = fmaxf(v1, 0.f);
    float nrm = sqrtf(v0 * v0 + v1 * v1);
    float inv = 1.f / fmaxf(nrm, 1e-12f);
    hout[(size_t)n * 64 + dd] = 0.5f * (v0 + v1) * inv;
}

// ============ layer 2 collapsed: node-mean of agg, then tiny GEMM ============
__global__ void aggmean_kernel() {
    int t = blockIdx.y;
    int col = threadIdx.x;   // 128
    float s = 0.f;
    for (int n = blockIdx.x; n < NN; n += gridDim.x)
        s += d_agg[((size_t)t * NN + n) * 128 + col];
    atomicAdd(&d_msum[t * 128 + col], s);
}

// out[d] = (1/8) sum_t sum_h (mean_n agg)[t,h,:] @ W2[t,:,h*64+d] + bias mean
__global__ void final_kernel(const float* __restrict__ W2,
                             const float* __restrict__ b2,
                             float* __restrict__ out) {
    __shared__ float sm[256];
    int tid = threadIdx.x;        // 256
    int dd = tid & 63;
    int part = tid >> 6;          // 0..3 -> etype
    int t = part;
    float s = 0.f;
#pragma unroll
    for (int hh = 0; hh < 2; hh++) {
        for (int k = 0; k < 64; k++) {
            float m = d_msum[t * 128 + hh * 64 + k];
            s = fmaf(m, W2[((size_t)(t * 64 + k)) * 128 + hh * 64 + dd], s);
        }
    }
    sm[tid] = s;
    __syncthreads();
    if (part == 0) {
        float tot = sm[dd] + sm[64 + dd] + sm[128 + dd] + sm[192 + dd];
        tot *= 0.125f / (float)NN;     // (1/4 etypes)(1/2 heads)(msum is a sum over n)
        float bb = 0.f;
#pragma unroll
        for (int tt = 0; tt < TT; tt++)
            bb += b2[tt * 128 + dd] + b2[tt * 128 + 64 + dd];
        out[dd] = tot + bb * 0.125f;
    }
}

// ================= driver =================
extern "C" void kernel_launch(void* const* d_in, const int* in_sizes, int n_in,
                              void* d_out, int out_size) {
    const float* x   = (const float*)d_in[0];
    const int* edges = (const int*)  d_in[1];
    const float* W0  = (const float*)d_in[2];
    const float* al0 = (const float*)d_in[3];
    const float* ar0 = (const float*)d_in[4];
    const float* b0  = (const float*)d_in[5];
    const float* W1  = (const float*)d_in[6];
    const float* al1 = (const float*)d_in[7];
    const float* ar1 = (const float*)d_in[8];
    const float* b1  = (const float*)d_in[9];
    const float* W2  = (const float*)d_in[10];
    const float* al2 = (const float*)d_in[11];
    const float* ar2 = (const float*)d_in[12];
    const float* b2  = (const float*)d_in[13];
    float* out = (float*)d_out;

    void* hptr = nullptr;
    cudaGetSymbolAddress(&hptr, d_hbuf);
    float* h1 = (float*)hptr;
    float* h2 = h1 + (size_t)NN * 64;

    const int eg = (ETOT + 255) / 256;
    const int ng = (NN * 32 + 255) / 256;       // eler: warp per node
    const int sg = (ROWS * 32 + 255) / 256;     // segment2: warp per row
    const int gg = (NN + 31) / 32;              // out gemm
    const int pg = (NN * 64 + 255) / 256;

    // ---- CSR build (edges fixed across layers) ----
    zero_deg_kernel<<<(ROWS + 255) / 256, 256>>>();
    hist_kernel<<<eg, 256>>>(edges);
    scan_k1<<<NBLK, 256>>>();
    scan_k2<<<1, 256>>>();
    scan_k3<<<NBLK, 256>>>();
    scatter_kernel<<<eg, 256>>>(edges);

    // ---- layer 0 (K=23) ----
    walwar_kernel<<<1, TT * 2 * 23>>>(W0, al0, ar0, 23);
    eler_kernel<23><<<ng, 256>>>(x);
    edgeexp_kernel<<<eg, 256>>>(edges);
    segment2_kernel<23><<<sg, 256>>>(x);
    out_gemm_kernel<23><<<gg, 256>>>(W0);
    post_kernel<<<pg, 256>>>(b0, h1);

    // ---- layer 1 (K=64) ----
    walwar_kernel<<<1, TT * 2 * 64>>>(W1, al1, ar1, 64);
    eler_kernel<64><<<ng, 256>>>(h1);
    edgeexp_kernel<<<eg, 256>>>(edges);
    segment2_kernel<64><<<sg, 256>>>(h1);
    out_gemm_kernel<64><<<gg, 256>>>(W1);
    post_kernel<<<pg, 256>>>(b1, h2);

    // ---- layer 2 (K=64, collapsed output) ----
    walwar_kernel<<<1, TT * 2 * 64>>>(W2, al2, ar2, 64);
    eler_kernel<64><<<ng, 256>>>(h2);
    edgeexp_kernel<<<eg, 256>>>(edges);
    segment2_kernel<64><<<sg, 256>>>(h2);
    {
        dim3 ag(512, TT);
        aggmean_kernel<<<ag, 128>>>();
    }
    final_kernel<<<1, 256>>>(W2, b2, out);
}

// round 5
// speedup vs baseline: 2.5672x; 1.1164x over previous
#include <cuda_runtime.h>
#include <cuda_bf16.h>

#define NN 50000
#define EE 250000
#define TT 4
#define ROWS (TT*NN)
#define ETOT (TT*EE)
#define CHUNK 1024
#define NBLK ((ROWS + CHUNK - 1) / CHUNK)   // 196

// ---------------- scratch (static device globals) ----------------
__device__ float          d_el[ROWS * 2];
__device__ float          d_er[ROWS * 2];
__device__ float          d_wal[TT * 2 * 64];
__device__ float          d_war[TT * 2 * 64];
__device__ __nv_bfloat16  d_aggh[(size_t)ROWS * 128];   // 51.2MB -> L2-resident
__device__ float          d_hbuf[2 * (size_t)NN * 64];
__device__ float          d_msum[TT * 128];
__device__ int            d_deg[ROWS];
__device__ int            d_rowptr[ROWS + 1];
__device__ int            d_cursor[ROWS];
__device__ int            d_csrc[ETOT];
__device__ int            d_bsum[256];

// ---------------- f32x2 packed helpers ----------------
__device__ __forceinline__ unsigned long long f32x2_bcast(float x) {
    unsigned long long r;
    asm("mov.b64 %0, {%1, %1};" : "=l"(r) : "f"(x));
    return r;
}
__device__ __forceinline__ float2 f32x2_unpack(unsigned long long v) {
    float2 f;
    asm("mov.b64 {%0, %1}, %2;" : "=f"(f.x), "=f"(f.y) : "l"(v));
    return f;
}
#define FMA2(d, a, b, c) \
    asm("fma.rn.f32x2 %0, %1, %2, %3;" : "=l"(d) : "l"(a), "l"(b), "l"(c))

__device__ __forceinline__ float lrelu(float x) { return x > 0.f ? x : 0.2f * x; }

// ================= CSR build (edges constant across layers) =================
__global__ void zero_deg_kernel() {
    int i = blockIdx.x * blockDim.x + threadIdx.x;
    if (i < ROWS) d_deg[i] = 0;
    if (i < TT * 128) d_msum[i] = 0.f;
}

__global__ void hist_kernel(const int* __restrict__ edges) {
    int i = blockIdx.x * blockDim.x + threadIdx.x;
    if (i >= ETOT) return;
    int t = i / EE, e = i - t * EE;
    int d = edges[(size_t)t * 2 * EE + EE + e];
    atomicAdd(&d_deg[t * NN + d], 1);
}

__global__ void scan_k1() {
    __shared__ int sm[256];
    int b = blockIdx.x, tid = threadIdx.x;
    int s = 0;
#pragma unroll
    for (int i = 0; i < 4; i++) {
        int idx = b * CHUNK + tid + 256 * i;
        if (idx < ROWS) s += d_deg[idx];
    }
    sm[tid] = s;
    __syncthreads();
    for (int o = 128; o > 0; o >>= 1) {
        if (tid < o) sm[tid] += sm[tid + o];
        __syncthreads();
    }
    if (tid == 0) d_bsum[b] = sm[0];
}

__global__ void scan_k2() {
    __shared__ int sm[256];
    int tid = threadIdx.x;
    int own = (tid < NBLK) ? d_bsum[tid] : 0;
    sm[tid] = own;
    __syncthreads();
    for (int o = 1; o < 256; o <<= 1) {
        int add = (tid >= o) ? sm[tid - o] : 0;
        __syncthreads();
        sm[tid] += add;
        __syncthreads();
    }
    if (tid < NBLK) d_bsum[tid] = sm[tid] - own;   // exclusive
}

__global__ void scan_k3() {
    __shared__ int sm[256];
    int b = blockIdx.x, tid = threadIdx.x;
    int base = b * CHUNK + tid * 4;
    int v[4], p[4], s = 0;
#pragma unroll
    for (int i = 0; i < 4; i++) {
        int idx = base + i;
        v[i] = (idx < ROWS) ? d_deg[idx] : 0;
        p[i] = s;
        s += v[i];
    }
    sm[tid] = s;
    __syncthreads();
    for (int o = 1; o < 256; o <<= 1) {
        int add = (tid >= o) ? sm[tid - o] : 0;
        __syncthreads();
        sm[tid] += add;
        __syncthreads();
    }
    int off = d_bsum[b] + (tid ? sm[tid - 1] : 0);
#pragma unroll
    for (int i = 0; i < 4; i++) {
        int idx = base + i;
        if (idx < ROWS) {
            d_rowptr[idx] = off + p[i];
            d_cursor[idx] = off + p[i];
        }
    }
    if (b == 0 && tid == 0) d_rowptr[ROWS] = ETOT;
}

__global__ void scatter_kernel(const int* __restrict__ edges) {
    int i = blockIdx.x * blockDim.x + threadIdx.x;
    if (i >= ETOT) return;
    int t = i / EE, e = i - t * EE;
    int s = edges[(size_t)t * 2 * EE + e];
    int d = edges[(size_t)t * 2 * EE + EE + e];
    int pos = atomicAdd(&d_cursor[t * NN + d], 1);
    d_csrc[pos] = s;
}

// ================= per-layer kernels =================
__global__ void walwar_kernel(const float* __restrict__ W,
                              const float* __restrict__ al,
                              const float* __restrict__ ar, int K) {
    int tid = threadIdx.x;
    if (tid >= TT * 2 * K) return;
    int t = tid / (2 * K);
    int rem = tid - t * 2 * K;
    int hh = rem / K;
    int k = rem - hh * K;
    float sl = 0.f, sr = 0.f;
    const float* Wr = W + ((size_t)(t * K + k)) * 128 + hh * 64;
    const float* alr = al + (t * 2 + hh) * 64;
    const float* arr = ar + (t * 2 + hh) * 64;
#pragma unroll
    for (int j = 0; j < 64; j++) {
        float w = Wr[j];
        sl = fmaf(w, alr[j], sl);
        sr = fmaf(w, arr[j], sr);
    }
    d_wal[(t * 2 + hh) * 64 + k] = sl;
    d_war[(t * 2 + hh) * 64 + k] = sr;
}

// el/er per node; one warp per node
template <int K>
__global__ void eler_kernel(const float* __restrict__ h) {
    __shared__ float swal[512], swar[512];
    int tid = threadIdx.x;
    if (tid < 256) {
        swal[tid] = d_wal[tid];       swal[tid + 256] = d_wal[tid + 256];
        swar[tid] = d_war[tid];       swar[tid + 256] = d_war[tid + 256];
    }
    __syncthreads();
    int lane = tid & 31;
    int n = (blockIdx.x * blockDim.x + tid) >> 5;
    if (n >= NN) return;
    float h0 = (lane < K) ? h[(size_t)n * K + lane] : 0.f;
    float h1 = (K > 32 && lane + 32 < K) ? h[(size_t)n * K + lane + 32] : 0.f;
#pragma unroll
    for (int t = 0; t < TT; t++) {
#pragma unroll
        for (int hh = 0; hh < 2; hh++) {
            int base = (t * 2 + hh) * 64;
            float pl = h0 * swal[base + lane];
            float pr = h0 * swar[base + lane];
            if (K > 32) {
                pl = fmaf(h1, swal[base + lane + 32], pl);
                pr = fmaf(h1, swar[base + lane + 32], pr);
            }
#pragma unroll
            for (int o = 16; o > 0; o >>= 1) {
                pl += __shfl_down_sync(0xffffffffu, pl, o);
                pr += __shfl_down_sync(0xffffffffu, pr, o);
            }
            if (lane == 0) {
                d_el[((size_t)t * NN + n) * 2 + hh] = pl;
                d_er[((size_t)t * NN + n) * 2 + hh] = pr;
            }
        }
    }
}

// one warp per row: inline exp(lrelu(el[src]+er)), single-pass accumulate,
// normalize at end, bf16 store. No separate edge pass, no atomics.
template <int K>
__global__ void segment2_kernel(const float* __restrict__ h) {
    int tid = threadIdx.x;
    int lane = tid & 31;
    int row = (blockIdx.x * blockDim.x + tid) >> 5;   // t*NN + d
    if (row >= ROWS) return;
    int t = row / NN;
    int beg = d_rowptr[row], end = d_rowptr[row + 1];
    float2 er2 = *(const float2*)&d_er[(size_t)row * 2];

    float den0 = 0.f, den1 = 0.f;
    float2 a0 = make_float2(0.f, 0.f), a1 = make_float2(0.f, 0.f);
    float as0 = 0.f, as1 = 0.f;

    // software pipeline: prefetch next (src, el, h) while consuming current
    float2 el_c = make_float2(0.f, 0.f);
    float2 hv_c = make_float2(0.f, 0.f);
    float  hs_c = 0.f;
    if (beg < end) {
        int s = d_csrc[beg];
        el_c = *(const float2*)&d_el[((size_t)t * NN + s) * 2];
        if (K == 64) hv_c = ((const float2*)h)[(size_t)s * 32 + lane];
        else         hs_c = (lane < K) ? h[(size_t)s * K + lane] : 0.f;
    }
    for (int j = beg; j < end; j++) {
        float2 el_n = make_float2(0.f, 0.f), hv_n = make_float2(0.f, 0.f);
        float hs_n = 0.f;
        if (j + 1 < end) {
            int sn = d_csrc[j + 1];
            el_n = *(const float2*)&d_el[((size_t)t * NN + sn) * 2];
            if (K == 64) hv_n = ((const float2*)h)[(size_t)sn * 32 + lane];
            else         hs_n = (lane < K) ? h[(size_t)sn * K + lane] : 0.f;
        }
        float w0 = __expf(lrelu(el_c.x + er2.x));
        float w1 = __expf(lrelu(el_c.y + er2.y));
        den0 += w0;
        den1 += w1;
        if (K == 64) {
            a0.x = fmaf(w0, hv_c.x, a0.x);
            a0.y = fmaf(w0, hv_c.y, a0.y);
            a1.x = fmaf(w1, hv_c.x, a1.x);
            a1.y = fmaf(w1, hv_c.y, a1.y);
        } else {
            as0 = fmaf(w0, hs_c, as0);
            as1 = fmaf(w1, hs_c, as1);
        }
        el_c = el_n; hv_c = hv_n; hs_c = hs_n;
    }
    float inv0 = (end > beg) ? 1.f / den0 : 0.f;
    float inv1 = (end > beg) ? 1.f / den1 : 0.f;
    if (K == 64) {
        __nv_bfloat162* p = (__nv_bfloat162*)&d_aggh[(size_t)row * 128];
        p[lane]      = __floats2bfloat162_rn(a0.x * inv0, a0.y * inv0);
        p[32 + lane] = __floats2bfloat162_rn(a1.x * inv1, a1.y * inv1);
    } else {
        size_t base = (size_t)row * 2 * K;
        if (lane < K) {
            d_aggh[base + lane]     = __float2bfloat16(as0 * inv0);
            d_aggh[base + K + lane] = __float2bfloat16(as1 * inv1);
        }
    }
}

// acc[n,col] = sum_t sum_k agg[t,n,head(col),k] * W[t,k,col], then fused
// post: +bias/4, relu, L2-norm over heads, head-mean -> hout (layers 0,1)
template <int K>
__global__ void out_gemm_kernel(const float* __restrict__ W,
                                const float* __restrict__ b,
                                float* __restrict__ hout) {
    __shared__ __align__(16) float Ws[K * 128];
    __shared__ __align__(16) float As[32 * 128];   // tiles (stride 2K) then Acc (stride 128)
    int tid = threadIdx.x;
    int cp = tid & 63;          // column pair: cols 2cp,2cp+1 (and post dd=cp)
    int g = tid >> 6;           // node group: nodes g*8..g*8+7
    int head = cp >> 5;
    int nbase = blockIdx.x * 32;
    int nvalid = min(32, NN - nbase);

    unsigned long long acc[8];
#pragma unroll
    for (int i = 0; i < 8; i++) acc[i] = 0ull;

    for (int t = 0; t < TT; t++) {
        const float* Wg = W + (size_t)t * K * 128;
        for (int i = tid; i < K * 128 / 4; i += 256)
            ((float4*)Ws)[i] = ((const float4*)Wg)[i];
        const __nv_bfloat162* Ag2 =
            (const __nv_bfloat162*)(d_aggh + ((size_t)t * NN + nbase) * 2 * K);
        int tot2 = nvalid * K;              // bf162 units
        for (int i = tid; i < tot2; i += 256)
            ((float2*)As)[i] = __bfloat1622float2(Ag2[i]);
        __syncthreads();

        const float* arow = As + (g * 8) * 2 * K + head * K;
        for (int k = 0; k < K; k++) {
            unsigned long long w = *(const unsigned long long*)&Ws[k * 128 + 2 * cp];
#pragma unroll
            for (int i = 0; i < 8; i++) {
                unsigned long long a = f32x2_bcast(arow[i * 2 * K + k]);
                FMA2(acc[i], a, w, acc[i]);
            }
        }
        __syncthreads();
    }

    // stage result tile into As (now stride 128) and run post in-block
#pragma unroll
    for (int i = 0; i < 8; i++) {
        float2 v = f32x2_unpack(acc[i]);
        *(float2*)&As[(g * 8 + i) * 128 + 2 * cp] = v;
    }
    __syncthreads();

    int dd = cp;
    float bm0 = 0.f, bm1 = 0.f;
#pragma unroll
    for (int t = 0; t < TT; t++) {
        bm0 += b[t * 128 + dd];
        bm1 += b[t * 128 + 64 + dd];
    }
    bm0 *= 0.25f; bm1 *= 0.25f;
#pragma unroll
    for (int i = 0; i < 8; i++) {
        int n = nbase + g * 8 + i;
        if (n < NN) {
            float v0 = As[(g * 8 + i) * 128 + dd] * 0.25f + bm0;
            float v1 = As[(g * 8 + i) * 128 + 64 + dd] * 0.25f + bm1;
            v0 = fmaxf(v0, 0.f);
            v1 = fmaxf(v1, 0.f);
            float nrm = sqrtf(v0 * v0 + v1 * v1);
            float inv = 1.f / fmaxf(nrm, 1e-12f);
            hout[(size_t)n * 64 + dd] = 0.5f * (v0 + v1) * inv;
        }
    }
}

// ============ layer 2 collapsed: node-mean of agg, then tiny GEMM ============
__global__ void aggmean_kernel() {
    int t = blockIdx.y;
    int col = threadIdx.x;   // 128
    float s = 0.f;
    for (int n = blockIdx.x; n < NN; n += gridDim.x)
        s += __bfloat162float(d_aggh[((size_t)t * NN + n) * 128 + col]);
    atomicAdd(&d_msum[t * 128 + col], s);
}

__global__ void final_kernel(const float* __restrict__ W2,
                             const float* __restrict__ b2,
                             float* __restrict__ out) {
    __shared__ float sm[256];
    int tid = threadIdx.x;        // 256
    int dd = tid & 63;
    int part = tid >> 6;          // 0..3 -> etype
    int t = part;
    float s = 0.f;
#pragma unroll
    for (int hh = 0; hh < 2; hh++) {
        for (int k = 0; k < 64; k++) {
            float m = d_msum[t * 128 + hh * 64 + k];
            s = fmaf(m, W2[((size_t)(t * 64 + k)) * 128 + hh * 64 + dd], s);
        }
    }
    sm[tid] = s;
    __syncthreads();
    if (part == 0) {
        float tot = sm[dd] + sm[64 + dd] + sm[128 + dd] + sm[192 + dd];
        tot *= 0.125f / (float)NN;
        float bb = 0.f;
#pragma unroll
        for (int tt = 0; tt < TT; tt++)
            bb += b2[tt * 128 + dd] + b2[tt * 128 + 64 + dd];
        out[dd] = tot + bb * 0.125f;
    }
}

// ================= driver =================
extern "C" void kernel_launch(void* const* d_in, const int* in_sizes, int n_in,
                              void* d_out, int out_size) {
    const float* x   = (const float*)d_in[0];
    const int* edges = (const int*)  d_in[1];
    const float* W0  = (const float*)d_in[2];
    const float* al0 = (const float*)d_in[3];
    const float* ar0 = (const float*)d_in[4];
    const float* b0  = (const float*)d_in[5];
    const float* W1  = (const float*)d_in[6];
    const float* al1 = (const float*)d_in[7];
    const float* ar1 = (const float*)d_in[8];
    const float* b1  = (const float*)d_in[9];
    const float* W2  = (const float*)d_in[10];
    const float* al2 = (const float*)d_in[11];
    const float* ar2 = (const float*)d_in[12];
    const float* b2  = (const float*)d_in[13];
    float* out = (float*)d_out;

    void* hptr = nullptr;
    cudaGetSymbolAddress(&hptr, d_hbuf);
    float* h1 = (float*)hptr;
    float* h2 = h1 + (size_t)NN * 64;

    const int eg = (ETOT + 255) / 256;
    const int ng = (NN * 32 + 255) / 256;       // eler: warp per node
    const int sg = (ROWS * 32 + 255) / 256;     // segment2: warp per row
    const int gg = (NN + 31) / 32;              // out gemm
    const int zg = (ROWS + 255) / 256;

    // ---- CSR build (edges fixed across layers) ----
    zero_deg_kernel<<<zg, 256>>>();
    hist_kernel<<<eg, 256>>>(edges);
    scan_k1<<<NBLK, 256>>>();
    scan_k2<<<1, 256>>>();
    scan_k3<<<NBLK, 256>>>();
    scatter_kernel<<<eg, 256>>>(edges);

    // ---- layer 0 (K=23) ----
    walwar_kernel<<<1, TT * 2 * 23>>>(W0, al0, ar0, 23);
    eler_kernel<23><<<ng, 256>>>(x);
    segment2_kernel<23><<<sg, 256>>>(x);
    out_gemm_kernel<23><<<gg, 256>>>(W0, b0, h1);

    // ---- layer 1 (K=64) ----
    walwar_kernel<<<1, TT * 2 * 64>>>(W1, al1, ar1, 64);
    eler_kernel<64><<<ng, 256>>>(h1);
    segment2_kernel<64><<<sg, 256>>>(h1);
    out_gemm_kernel<64><<<gg, 256>>>(W1, b1, h2);

    // ---- layer 2 (K=64, collapsed output) ----
    walwar_kernel<<<1, TT * 2 * 64>>>(W2, al2, ar2, 64);
    eler_kernel<64><<<ng, 256>>>(h2);
    segment2_kernel<64><<<sg, 256>>>(h2);
    {
        dim3 ag(512, TT);
        aggmean_kernel<<<ag, 128>>>();
    }
    final_kernel<<<1, 256>>>(W2, b2, out);
}

// round 6
// speedup vs baseline: 2.8117x; 1.0952x over previous
#include <cuda_runtime.h>
#include <cuda_fp16.h>

#define NN 50000
#define EE 250000
#define TT 4
#define ROWS (TT*NN)
#define ETOT (TT*EE)
#define CHUNK 1024
#define NBLK ((ROWS + CHUNK - 1) / CHUNK)   // 196

// ---------------- scratch (static device globals) ----------------
__device__ float  d_el[ROWS * 2];
__device__ float  d_er[ROWS * 2];
__device__ float  d_wal[3 * 512];
__device__ float  d_war[3 * 512];
__device__ __half d_aggh[(size_t)ROWS * 128];   // 51.2MB, L2-resident
__device__ float  d_hbuf[2 * (size_t)NN * 64];
__device__ float  d_msum[TT * 128];
__device__ int    d_deg[ROWS];
__device__ int    d_rowptr[ROWS + 1];
__device__ int    d_cursor[ROWS];
__device__ int    d_csrc[ETOT];
__device__ int    d_bsum[NBLK];
__device__ int    d_ctr;

// ---------------- f32x2 packed helpers ----------------
__device__ __forceinline__ unsigned long long f32x2_bcast(float x) {
    unsigned long long r;
    asm("mov.b64 %0, {%1, %1};" : "=l"(r) : "f"(x));
    return r;
}
__device__ __forceinline__ float2 f32x2_unpack(unsigned long long v) {
    float2 f;
    asm("mov.b64 {%0, %1}, %2;" : "=f"(f.x), "=f"(f.y) : "l"(v));
    return f;
}
#define FMA2(d, a, b, c) \
    asm("fma.rn.f32x2 %0, %1, %2, %3;" : "=l"(d) : "l"(a), "l"(b), "l"(c))

__device__ __forceinline__ float lrelu(float x) { return x > 0.f ? x : 0.2f * x; }

// ========== prep: zero deg/msum/ctr + wal/war for all 3 layers ==========
__global__ void prep_kernel(const float* __restrict__ W0, const float* __restrict__ al0, const float* __restrict__ ar0,
                            const float* __restrict__ W1, const float* __restrict__ al1, const float* __restrict__ ar1,
                            const float* __restrict__ W2, const float* __restrict__ al2, const float* __restrict__ ar2) {
    int gi = blockIdx.x * blockDim.x + threadIdx.x;
    int stride = gridDim.x * blockDim.x;
    for (int j = gi; j < ROWS; j += stride) d_deg[j] = 0;
    if (gi < TT * 128) d_msum[gi] = 0.f;
    if (gi == 0) d_ctr = 0;

    if (blockIdx.x < 3) {
        int L = blockIdx.x;
        const float* W  = (L == 0) ? W0  : (L == 1) ? W1  : W2;
        const float* al = (L == 0) ? al0 : (L == 1) ? al1 : al2;
        const float* ar = (L == 0) ? ar0 : (L == 1) ? ar1 : ar2;
        int K = (L == 0) ? 23 : 64;
        for (int idx = threadIdx.x; idx < TT * 2 * K; idx += blockDim.x) {
            int t = idx / (2 * K);
            int rem = idx - t * 2 * K;
            int hh = rem / K;
            int k = rem - hh * K;
            float sl = 0.f, sr = 0.f;
            const float* Wr = W + ((size_t)(t * K + k)) * 128 + hh * 64;
            const float* alr = al + (t * 2 + hh) * 64;
            const float* arr = ar + (t * 2 + hh) * 64;
#pragma unroll
            for (int j = 0; j < 64; j++) {
                float w = Wr[j];
                sl = fmaf(w, alr[j], sl);
                sr = fmaf(w, arr[j], sr);
            }
            d_wal[L * 512 + (t * 2 + hh) * 64 + k] = sl;
            d_war[L * 512 + (t * 2 + hh) * 64 + k] = sr;
        }
    }
}

// ================= CSR build =================
__global__ void hist_kernel(const int* __restrict__ edges) {
    int i = blockIdx.x * blockDim.x + threadIdx.x;
    if (i >= ETOT) return;
    int t = i / EE, e = i - t * EE;
    int d = edges[(size_t)t * 2 * EE + EE + e];
    atomicAdd(&d_deg[t * NN + d], 1);
}

__global__ void scan_k1() {
    __shared__ int sm[256];
    int b = blockIdx.x, tid = threadIdx.x;
    int s = 0;
#pragma unroll
    for (int i = 0; i < 4; i++) {
        int idx = b * CHUNK + tid + 256 * i;
        if (idx < ROWS) s += d_deg[idx];
    }
    sm[tid] = s;
    __syncthreads();
    for (int o = 128; o > 0; o >>= 1) {
        if (tid < o) sm[tid] += sm[tid + o];
        __syncthreads();
    }
    if (tid == 0) d_bsum[b] = sm[0];
}

// scan_k3 with inline block-prefix of bsum (removes scan_k2 launch)
__global__ void scan_k3b() {
    __shared__ int sp[256];
    __shared__ int sm[256];
    int b = blockIdx.x, tid = threadIdx.x;
    int v = (tid < b) ? d_bsum[tid] : 0;   // b < NBLK <= 256
    sp[tid] = v;
    __syncthreads();
    for (int o = 128; o > 0; o >>= 1) {
        if (tid < o) sp[tid] += sp[tid + o];
        __syncthreads();
    }
    int pre = sp[0];

    int base = b * CHUNK + tid * 4;
    int vv[4], p[4], s = 0;
#pragma unroll
    for (int i = 0; i < 4; i++) {
        int idx = base + i;
        vv[i] = (idx < ROWS) ? d_deg[idx] : 0;
        p[i] = s;
        s += vv[i];
    }
    sm[tid] = s;
    __syncthreads();
    for (int o = 1; o < 256; o <<= 1) {
        int add = (tid >= o) ? sm[tid - o] : 0;
        __syncthreads();
        sm[tid] += add;
        __syncthreads();
    }
    int off = pre + (tid ? sm[tid - 1] : 0);
#pragma unroll
    for (int i = 0; i < 4; i++) {
        int idx = base + i;
        if (idx < ROWS) {
            d_rowptr[idx] = off + p[i];
            d_cursor[idx] = off + p[i];
        }
    }
    if (b == 0 && tid == 0) d_rowptr[ROWS] = ETOT;
}

__global__ void scatter_kernel(const int* __restrict__ edges) {
    int i = blockIdx.x * blockDim.x + threadIdx.x;
    if (i >= ETOT) return;
    int t = i / EE, e = i - t * EE;
    int s = edges[(size_t)t * 2 * EE + e];
    int d = edges[(size_t)t * 2 * EE + EE + e];
    int pos = atomicAdd(&d_cursor[t * NN + d], 1);
    d_csrc[pos] = s;
}

// ================= per-layer kernels =================
// thread-per-node el/er: h row in regs, wal/war broadcast from smem
template <int K>
__global__ void eler2_kernel(const float* __restrict__ h, int layer) {
    __shared__ float swal[512], swar[512];
    int tid = threadIdx.x;
    swal[tid] = d_wal[layer * 512 + tid];
    swal[tid + 256] = d_wal[layer * 512 + tid + 256];
    swar[tid] = d_war[layer * 512 + tid];
    swar[tid + 256] = d_war[layer * 512 + tid + 256];
    __syncthreads();
    int n = blockIdx.x * blockDim.x + tid;
    if (n >= NN) return;
    float hreg[K];
    if (K == 64) {
        const float4* hr = (const float4*)(h + (size_t)n * K);
#pragma unroll
        for (int i = 0; i < K / 4; i++) {
            float4 v = hr[i];
            hreg[4 * i] = v.x; hreg[4 * i + 1] = v.y;
            hreg[4 * i + 2] = v.z; hreg[4 * i + 3] = v.w;
        }
    } else {
#pragma unroll
        for (int i = 0; i < K; i++) hreg[i] = h[(size_t)n * K + i];
    }
#pragma unroll
    for (int t = 0; t < TT; t++) {
        float pl0 = 0.f, pl1 = 0.f, pr0 = 0.f, pr1 = 0.f;
        int b0 = (t * 2) * 64, b1 = (t * 2 + 1) * 64;
#pragma unroll
        for (int k = 0; k < K; k++) {
            float hk = hreg[k];
            pl0 = fmaf(hk, swal[b0 + k], pl0);
            pl1 = fmaf(hk, swal[b1 + k], pl1);
            pr0 = fmaf(hk, swar[b0 + k], pr0);
            pr1 = fmaf(hk, swar[b1 + k], pr1);
        }
        *(float2*)&d_el[((size_t)t * NN + n) * 2] = make_float2(pl0, pl1);
        *(float2*)&d_er[((size_t)t * NN + n) * 2] = make_float2(pr0, pr1);
    }
}

// warp-per-row: inline exp(lrelu(el[src]+er)), single-pass, fp16 store
template <int K>
__global__ void segment2_kernel(const float* __restrict__ h) {
    int tid = threadIdx.x;
    int lane = tid & 31;
    int row = (blockIdx.x * blockDim.x + tid) >> 5;   // t*NN + d
    if (row >= ROWS) return;
    int t = row / NN;
    int beg = d_rowptr[row], end = d_rowptr[row + 1];
    float2 er2 = *(const float2*)&d_er[(size_t)row * 2];

    float den0 = 0.f, den1 = 0.f;
    float2 a0 = make_float2(0.f, 0.f), a1 = make_float2(0.f, 0.f);
    float as0 = 0.f, as1 = 0.f;

    float2 el_c = make_float2(0.f, 0.f);
    float2 hv_c = make_float2(0.f, 0.f);
    float  hs_c = 0.f;
    if (beg < end) {
        int s = d_csrc[beg];
        el_c = *(const float2*)&d_el[((size_t)t * NN + s) * 2];
        if (K == 64) hv_c = ((const float2*)h)[(size_t)s * 32 + lane];
        else         hs_c = (lane < K) ? h[(size_t)s * K + lane] : 0.f;
    }
    for (int j = beg; j < end; j++) {
        float2 el_n = make_float2(0.f, 0.f), hv_n = make_float2(0.f, 0.f);
        float hs_n = 0.f;
        if (j + 1 < end) {
            int sn = d_csrc[j + 1];
            el_n = *(const float2*)&d_el[((size_t)t * NN + sn) * 2];
            if (K == 64) hv_n = ((const float2*)h)[(size_t)sn * 32 + lane];
            else         hs_n = (lane < K) ? h[(size_t)sn * K + lane] : 0.f;
        }
        float w0 = __expf(lrelu(el_c.x + er2.x));
        float w1 = __expf(lrelu(el_c.y + er2.y));
        den0 += w0;
        den1 += w1;
        if (K == 64) {
            a0.x = fmaf(w0, hv_c.x, a0.x);
            a0.y = fmaf(w0, hv_c.y, a0.y);
            a1.x = fmaf(w1, hv_c.x, a1.x);
            a1.y = fmaf(w1, hv_c.y, a1.y);
        } else {
            as0 = fmaf(w0, hs_c, as0);
            as1 = fmaf(w1, hs_c, as1);
        }
        el_c = el_n; hv_c = hv_n; hs_c = hs_n;
    }
    float inv0 = (end > beg) ? 1.f / den0 : 0.f;
    float inv1 = (end > beg) ? 1.f / den1 : 0.f;
    if (K == 64) {
        __half2* p = (__half2*)&d_aggh[(size_t)row * 128];
        p[lane]      = __floats2half2_rn(a0.x * inv0, a0.y * inv0);
        p[32 + lane] = __floats2half2_rn(a1.x * inv1, a1.y * inv1);
    } else {
        size_t base = (size_t)row * 2 * K;
        if (lane < K) {
            d_aggh[base + lane]     = __float2half(as0 * inv0);
            d_aggh[base + K + lane] = __float2half(as1 * inv1);
        }
    }
}

// ===== out gemm: 64-node tile, thread = 8 nodes x 4 cols, K chunked =====
// fused post epilogue (layers 0,1): +bias/4, relu, L2-norm heads, head-mean
template <int K>
__global__ void out_gemm_kernel(const float* __restrict__ W,
                                const float* __restrict__ b,
                                float* __restrict__ hout) {
    constexpr int KC  = (K == 64) ? 32 : 23;    // k per chunk
    constexpr int NCH = (K == 64) ? 2 : 1;      // chunks
    constexpr int NS  = (K == 64) ? 68 : 46;    // As node stride (floats)
    constexpr int HS  = (K == 64) ? 34 : 23;    // As head stride

    __shared__ __align__(16) char sbuf[34816];
    float* Ws = (float*)sbuf;                       // KC*128 floats
    float* As = (float*)(sbuf + KC * 128 * 4);      // 64*NS floats
    float* St = (float*)sbuf;                       // 64*128 floats (aliased)

    int tid = threadIdx.x;
    int cq = tid & 31;          // col quad: cols 4cq..4cq+3
    int g = tid >> 5;           // node group: nodes g*8..g*8+7
    int head = cq >> 4;
    int nbase = blockIdx.x * 64;
    int nvalid = min(64, NN - nbase);

    unsigned long long acc[8][2];
#pragma unroll
    for (int i = 0; i < 8; i++) { acc[i][0] = 0ull; acc[i][1] = 0ull; }

    for (int t = 0; t < TT; t++) {
        for (int c = 0; c < NCH; c++) {
            // W chunk -> smem
            const float4* Wg4 = (const float4*)(W + (size_t)t * K * 128 + (size_t)c * KC * 128);
            for (int i = tid; i < KC * 128 / 4; i += 256)
                ((float4*)Ws)[i] = Wg4[i];
            // A chunk (fp16 -> f32) -> smem, bank-padded layout
            const __half2* Ag2 = (const __half2*)(d_aggh + ((size_t)t * NN + nbase) * 2 * K);
            if (K == 64) {
                int cnt = nvalid * 32;
                for (int i = tid; i < cnt; i += 256) {
                    int node = i >> 5, j = i & 31;
                    int hh = j >> 4, pos = j & 15;
                    float2 v = __half22float2(Ag2[node * 64 + hh * 32 + c * 16 + pos]);
                    *(float2*)&As[node * NS + hh * HS + pos * 2] = v;
                }
            } else {
                int cnt = nvalid * 23;
                for (int i = tid; i < cnt; i += 256) {
                    int node = i / 23, j = i - node * 23;
                    float2 v = __half22float2(Ag2[node * 23 + j]);
                    *(float2*)&As[node * NS + j * 2] = v;
                }
            }
            __syncthreads();

#pragma unroll 4
            for (int k = 0; k < KC; k++) {
                unsigned long long w0 = *(const unsigned long long*)&Ws[k * 128 + 4 * cq];
                unsigned long long w1 = *(const unsigned long long*)&Ws[k * 128 + 4 * cq + 2];
#pragma unroll
                for (int i = 0; i < 8; i++) {
                    unsigned long long a = f32x2_bcast(As[(g * 8 + i) * NS + head * HS + k]);
                    FMA2(acc[i][0], a, w0, acc[i][0]);
                    FMA2(acc[i][1], a, w1, acc[i][1]);
                }
            }
            __syncthreads();
        }
    }

    // stage 64x128 result tile and run fused post
#pragma unroll
    for (int i = 0; i < 8; i++) {
        int node = g * 8 + i;
        *(float2*)&St[node * 128 + 4 * cq]     = f32x2_unpack(acc[i][0]);
        *(float2*)&St[node * 128 + 4 * cq + 2] = f32x2_unpack(acc[i][1]);
    }
    __syncthreads();

    int dd = tid & 63;
    int q = tid >> 6;   // 0..3, 16 nodes each
    float bm0 = 0.f, bm1 = 0.f;
#pragma unroll
    for (int t = 0; t < TT; t++) {
        bm0 += b[t * 128 + dd];
        bm1 += b[t * 128 + 64 + dd];
    }
    bm0 *= 0.25f; bm1 *= 0.25f;
#pragma unroll
    for (int i = 0; i < 16; i++) {
        int node = q * 16 + i;
        int n = nbase + node;
        if (n < NN) {
            float v0 = St[node * 128 + dd] * 0.25f + bm0;
            float v1 = St[node * 128 + 64 + dd] * 0.25f + bm1;
            v0 = fmaxf(v0, 0.f);
            v1 = fmaxf(v1, 0.f);
            float nrm = sqrtf(v0 * v0 + v1 * v1);
            float inv = 1.f / fmaxf(nrm, 1e-12f);
            hout[(size_t)n * 64 + dd] = 0.5f * (v0 + v1) * inv;
        }
    }
}

// ==== layer 2 collapsed: node-mean of agg + final GEMM (last-block) ====
__global__ void aggmean_final_kernel(const float* __restrict__ W2,
                                     const float* __restrict__ b2,
                                     float* __restrict__ out) {
    int t = blockIdx.y;
    int col = threadIdx.x;   // 128
    float s = 0.f;
    for (int n = blockIdx.x; n < NN; n += gridDim.x)
        s += __half2float(d_aggh[((size_t)t * NN + n) * 128 + col]);
    atomicAdd(&d_msum[t * 128 + col], s);
    __threadfence();
    __syncthreads();
    __shared__ int flag;
    if (threadIdx.x == 0) {
        int v = atomicAdd(&d_ctr, 1);
        flag = (v == (int)(gridDim.x * gridDim.y) - 1);
    }
    __syncthreads();
    if (!flag) return;
    __threadfence();

    __shared__ float sm_m[512];
    for (int i = threadIdx.x; i < 512; i += 128) sm_m[i] = d_msum[i];
    __syncthreads();
    if (threadIdx.x < 64) {
        int dd = threadIdx.x;
        float sum = 0.f;
#pragma unroll
        for (int tt = 0; tt < TT; tt++)
#pragma unroll
            for (int hh = 0; hh < 2; hh++)
                for (int k = 0; k < 64; k++)
                    sum = fmaf(sm_m[tt * 128 + hh * 64 + k],
                               W2[((size_t)(tt * 64 + k)) * 128 + hh * 64 + dd], sum);
        sum *= 0.125f / (float)NN;
        float bb = 0.f;
#pragma unroll
        for (int tt = 0; tt < TT; tt++)
            bb += b2[tt * 128 + dd] + b2[tt * 128 + 64 + dd];
        out[dd] = sum + bb * 0.125f;
    }
}

// ================= driver =================
extern "C" void kernel_launch(void* const* d_in, const int* in_sizes, int n_in,
                              void* d_out, int out_size) {
    const float* x   = (const float*)d_in[0];
    const int* edges = (const int*)  d_in[1];
    const float* W0  = (const float*)d_in[2];
    const float* al0 = (const float*)d_in[3];
    const float* ar0 = (const float*)d_in[4];
    const float* b0  = (const float*)d_in[5];
    const float* W1  = (const float*)d_in[6];
    const float* al1 = (const float*)d_in[7];
    const float* ar1 = (const float*)d_in[8];
    const float* b1  = (const float*)d_in[9];
    const float* W2  = (const float*)d_in[10];
    const float* al2 = (const float*)d_in[11];
    const float* ar2 = (const float*)d_in[12];
    const float* b2  = (const float*)d_in[13];
    float* out = (float*)d_out;

    void* hptr = nullptr;
    cudaGetSymbolAddress(&hptr, d_hbuf);
    float* h1 = (float*)hptr;
    float* h2 = h1 + (size_t)NN * 64;

    const int eg = (ETOT + 255) / 256;
    const int ng = (NN + 255) / 256;            // eler2: thread per node
    const int sg = (ROWS * 32 + 255) / 256;     // segment2: warp per row
    const int gg = (NN + 63) / 64;              // out gemm: 64-node tiles

    prep_kernel<<<256, 256>>>(W0, al0, ar0, W1, al1, ar1, W2, al2, ar2);
    hist_kernel<<<eg, 256>>>(edges);
    scan_k1<<<NBLK, 256>>>();
    scan_k3b<<<NBLK, 256>>>();
    scatter_kernel<<<eg, 256>>>(edges);

    // ---- layer 0 (K=23) ----
    eler2_kernel<23><<<ng, 256>>>(x, 0);
    segment2_kernel<23><<<sg, 256>>>(x);
    out_gemm_kernel<23><<<gg, 256>>>(W0, b0, h1);

    // ---- layer 1 (K=64) ----
    eler2_kernel<64><<<ng, 256>>>(h1, 1);
    segment2_kernel<64><<<sg, 256>>>(h1);
    out_gemm_kernel<64><<<gg, 256>>>(W1, b1, h2);

    // ---- layer 2 (K=64, collapsed output) ----
    eler2_kernel<64><<<ng, 256>>>(h2, 2);
    segment2_kernel<64><<<sg, 256>>>(h2);
    {
        dim3 ag(512, TT);
        aggmean_final_kernel<<<ag, 128>>>(W2, b2, out);
    }
}

// round 8
// speedup vs baseline: 2.8253x; 1.0048x over previous
#include <cuda_runtime.h>
#include <cuda_fp16.h>

#define NN 50000
#define EE 250000
#define TT 4
#define ROWS (TT*NN)
#define ETOT (TT*EE)
#define CHUNK 1024
#define NBLK ((ROWS + CHUNK - 1) / CHUNK)   // 196

// ---------------- scratch (static device globals) ----------------
__device__ float  d_el[ROWS * 2];
__device__ float  d_er[ROWS * 2];
__device__ float  d_wal[3 * 512];
__device__ float  d_war[3 * 512];
__device__ __half d_aggh[(size_t)ROWS * 128];   // 51.2MB, L2-resident
__device__ float  d_hbuf[2 * (size_t)NN * 64];
__device__ float  d_msum[TT * 128];
__device__ int    d_deg[ROWS];
__device__ int    d_rowptr[ROWS + 1];
__device__ int    d_cursor[ROWS];
__device__ int    d_csrc[ETOT];
__device__ int    d_bsum[NBLK];
__device__ int    d_ctr;

// ---------------- f32x2 packed helpers ----------------
__device__ __forceinline__ unsigned long long f32x2_bcast(float x) {
    unsigned long long r;
    asm("mov.b64 %0, {%1, %1};" : "=l"(r) : "f"(x));
    return r;
}
__device__ __forceinline__ float2 f32x2_unpack(unsigned long long v) {
    float2 f;
    asm("mov.b64 {%0, %1}, %2;" : "=f"(f.x), "=f"(f.y) : "l"(v));
    return f;
}
#define FMA2(d, a, b, c) \
    asm("fma.rn.f32x2 %0, %1, %2, %3;" : "=l"(d) : "l"(a), "l"(b), "l"(c))

__device__ __forceinline__ float lrelu(float x) { return x > 0.f ? x : 0.2f * x; }

// ========== prep: zero deg/msum/ctr + wal/war for all 3 layers ==========
__global__ void prep_kernel(const float* __restrict__ W0, const float* __restrict__ al0, const float* __restrict__ ar0,
                            const float* __restrict__ W1, const float* __restrict__ al1, const float* __restrict__ ar1,
                            const float* __restrict__ W2, const float* __restrict__ al2, const float* __restrict__ ar2) {
    int gi = blockIdx.x * blockDim.x + threadIdx.x;
    int stride = gridDim.x * blockDim.x;
    for (int j = gi; j < ROWS; j += stride) d_deg[j] = 0;
    if (gi < TT * 128) d_msum[gi] = 0.f;
    if (gi == 0) d_ctr = 0;

    if (blockIdx.x < 3) {
        int L = blockIdx.x;
        const float* W  = (L == 0) ? W0  : (L == 1) ? W1  : W2;
        const float* al = (L == 0) ? al0 : (L == 1) ? al1 : al2;
        const float* ar = (L == 0) ? ar0 : (L == 1) ? ar1 : ar2;
        int K = (L == 0) ? 23 : 64;
        for (int idx = threadIdx.x; idx < TT * 2 * K; idx += blockDim.x) {
            int t = idx / (2 * K);
            int rem = idx - t * 2 * K;
            int hh = rem / K;
            int k = rem - hh * K;
            float sl = 0.f, sr = 0.f;
            const float* Wr = W + ((size_t)(t * K + k)) * 128 + hh * 64;
            const float* alr = al + (t * 2 + hh) * 64;
            const float* arr = ar + (t * 2 + hh) * 64;
#pragma unroll
            for (int j = 0; j < 64; j++) {
                float w = Wr[j];
                sl = fmaf(w, alr[j], sl);
                sr = fmaf(w, arr[j], sr);
            }
            d_wal[L * 512 + (t * 2 + hh) * 64 + k] = sl;
            d_war[L * 512 + (t * 2 + hh) * 64 + k] = sr;
        }
    }
}

// ================= CSR build =================
__global__ void hist_kernel(const int* __restrict__ edges) {
    int i = blockIdx.x * blockDim.x + threadIdx.x;
    if (i >= ETOT) return;
    int t = i / EE, e = i - t * EE;
    int d = edges[(size_t)t * 2 * EE + EE + e];
    atomicAdd(&d_deg[t * NN + d], 1);
}

__global__ void scan_k1() {
    __shared__ int sm[256];
    int b = blockIdx.x, tid = threadIdx.x;
    int s = 0;
#pragma unroll
    for (int i = 0; i < 4; i++) {
        int idx = b * CHUNK + tid + 256 * i;
        if (idx < ROWS) s += d_deg[idx];
    }
    sm[tid] = s;
    __syncthreads();
    for (int o = 128; o > 0; o >>= 1) {
        if (tid < o) sm[tid] += sm[tid + o];
        __syncthreads();
    }
    if (tid == 0) d_bsum[b] = sm[0];
}

// scan_k3 with inline block-prefix of bsum
__global__ void scan_k3b() {
    __shared__ int sp[256];
    __shared__ int sm[256];
    int b = blockIdx.x, tid = threadIdx.x;
    int v = (tid < b) ? d_bsum[tid] : 0;
    sp[tid] = v;
    __syncthreads();
    for (int o = 128; o > 0; o >>= 1) {
        if (tid < o) sp[tid] += sp[tid + o];
        __syncthreads();
    }
    int pre = sp[0];

    int base = b * CHUNK + tid * 4;
    int vv[4], p[4], s = 0;
#pragma unroll
    for (int i = 0; i < 4; i++) {
        int idx = base + i;
        vv[i] = (idx < ROWS) ? d_deg[idx] : 0;
        p[i] = s;
        s += vv[i];
    }
    sm[tid] = s;
    __syncthreads();
    for (int o = 1; o < 256; o <<= 1) {
        int add = (tid >= o) ? sm[tid - o] : 0;
        __syncthreads();
        sm[tid] += add;
        __syncthreads();
    }
    int off = pre + (tid ? sm[tid - 1] : 0);
#pragma unroll
    for (int i = 0; i < 4; i++) {
        int idx = base + i;
        if (idx < ROWS) {
            d_rowptr[idx] = off + p[i];
            d_cursor[idx] = off + p[i];
        }
    }
    if (b == 0 && tid == 0) d_rowptr[ROWS] = ETOT;
}

__global__ void scatter_kernel(const int* __restrict__ edges) {
    int i = blockIdx.x * blockDim.x + threadIdx.x;
    if (i >= ETOT) return;
    int t = i / EE, e = i - t * EE;
    int s = edges[(size_t)t * 2 * EE + e];
    int d = edges[(size_t)t * 2 * EE + EE + e];
    int pos = atomicAdd(&d_cursor[t * NN + d], 1);
    d_csrc[pos] = s;
}

// ================= per-layer kernels =================
// thread-per-node el/er: h row in regs, wal/war broadcast from smem
template <int K>
__global__ void eler2_kernel(const float* __restrict__ h, int layer) {
    __shared__ float swal[512], swar[512];
    int tid = threadIdx.x;
    swal[tid] = d_wal[layer * 512 + tid];
    swal[tid + 256] = d_wal[layer * 512 + tid + 256];
    swar[tid] = d_war[layer * 512 + tid];
    swar[tid + 256] = d_war[layer * 512 + tid + 256];
    __syncthreads();
    int n = blockIdx.x * blockDim.x + tid;
    if (n >= NN) return;
    float hreg[K];
    if (K == 64) {
        const float4* hr = (const float4*)(h + (size_t)n * K);
#pragma unroll
        for (int i = 0; i < K / 4; i++) {
            float4 v = hr[i];
            hreg[4 * i] = v.x; hreg[4 * i + 1] = v.y;
            hreg[4 * i + 2] = v.z; hreg[4 * i + 3] = v.w;
        }
    } else {
#pragma unroll
        for (int i = 0; i < K; i++) hreg[i] = h[(size_t)n * K + i];
    }
#pragma unroll
    for (int t = 0; t < TT; t++) {
        float pl0 = 0.f, pl1 = 0.f, pr0 = 0.f, pr1 = 0.f;
        int b0 = (t * 2) * 64, b1 = (t * 2 + 1) * 64;
#pragma unroll
        for (int k = 0; k < K; k++) {
            float hk = hreg[k];
            pl0 = fmaf(hk, swal[b0 + k], pl0);
            pl1 = fmaf(hk, swal[b1 + k], pl1);
            pr0 = fmaf(hk, swar[b0 + k], pr0);
            pr1 = fmaf(hk, swar[b1 + k], pr1);
        }
        *(float2*)&d_el[((size_t)t * NN + n) * 2] = make_float2(pl0, pl1);
        *(float2*)&d_er[((size_t)t * NN + n) * 2] = make_float2(pr0, pr1);
    }
}

// warp-per-row: inline exp(lrelu(el[src]+er)), single-pass, fp16 store.
// 2-wide unrolled edge loop: two independent load chains per iteration.
template <int K>
__global__ void segment2_kernel(const float* __restrict__ h) {
    int tid = threadIdx.x;
    int lane = tid & 31;
    int row = (blockIdx.x * blockDim.x + tid) >> 5;   // t*NN + d
    if (row >= ROWS) return;
    int t = row / NN;
    const float* elb = d_el + (size_t)t * NN * 2;
    int beg = d_rowptr[row], end = d_rowptr[row + 1];
    float2 er2 = *(const float2*)&d_er[(size_t)row * 2];

    float den0 = 0.f, den1 = 0.f;
    float2 a0 = make_float2(0.f, 0.f), a1 = make_float2(0.f, 0.f);
    float as0 = 0.f, as1 = 0.f;

    for (int j = beg; j < end; j += 2) {
        int sA = d_csrc[j];
        bool hasB = (j + 1 < end);
        int sB = hasB ? d_csrc[j + 1] : sA;
        float2 elA = *(const float2*)&elb[(size_t)sA * 2];
        float2 elB = *(const float2*)&elb[(size_t)sB * 2];
        float wA0 = __expf(lrelu(elA.x + er2.x));
        float wA1 = __expf(lrelu(elA.y + er2.y));
        float wB0 = hasB ? __expf(lrelu(elB.x + er2.x)) : 0.f;
        float wB1 = hasB ? __expf(lrelu(elB.y + er2.y)) : 0.f;
        den0 += wA0 + wB0;
        den1 += wA1 + wB1;
        if (K == 64) {
            float2 hA = ((const float2*)h)[(size_t)sA * 32 + lane];
            float2 hB = ((const float2*)h)[(size_t)sB * 32 + lane];
            a0.x = fmaf(wA0, hA.x, fmaf(wB0, hB.x, a0.x));
            a0.y = fmaf(wA0, hA.y, fmaf(wB0, hB.y, a0.y));
            a1.x = fmaf(wA1, hA.x, fmaf(wB1, hB.x, a1.x));
            a1.y = fmaf(wA1, hA.y, fmaf(wB1, hB.y, a1.y));
        } else {
            float hA = (lane < K) ? h[(size_t)sA * K + lane] : 0.f;
            float hB = (lane < K) ? h[(size_t)sB * K + lane] : 0.f;
            as0 = fmaf(wA0, hA, fmaf(wB0, hB, as0));
            as1 = fmaf(wA1, hA, fmaf(wB1, hB, as1));
        }
    }
    float inv0 = (end > beg) ? 1.f / den0 : 0.f;
    float inv1 = (end > beg) ? 1.f / den1 : 0.f;
    if (K == 64) {
        __half2* p = (__half2*)&d_aggh[(size_t)row * 128];
        p[lane]      = __floats2half2_rn(a0.x * inv0, a0.y * inv0);
        p[32 + lane] = __floats2half2_rn(a1.x * inv1, a1.y * inv1);
    } else {
        size_t base = (size_t)row * 2 * K;
        if (lane < K) {
            d_aggh[base + lane]     = __float2half(as0 * inv0);
            d_aggh[base + K + lane] = __float2half(as1 * inv1);
        }
    }
}

// ===== out gemm: 64-node tile, thread = 8 nodes x 4 cols, K chunked =====
// fused post epilogue (layers 0,1): +bias/4, relu, L2-norm heads, head-mean
template <int K>
__global__ void out_gemm_kernel(const float* __restrict__ W,
                                const float* __restrict__ b,
                                float* __restrict__ hout) {
    constexpr int KC  = (K == 64) ? 32 : 23;    // k per chunk
    constexpr int NCH = (K == 64) ? 2 : 1;      // chunks
    constexpr int NS  = (K == 64) ? 68 : 46;    // As node stride (floats)
    constexpr int HS  = (K == 64) ? 34 : 23;    // As head stride

    __shared__ __align__(16) char sbuf[34816];
    float* Ws = (float*)sbuf;                       // KC*128 floats
    float* As = (float*)(sbuf + KC * 128 * 4);      // 64*NS floats
    float* St = (float*)sbuf;                       // 64*128 floats (aliased)

    int tid = threadIdx.x;
    int cq = tid & 31;          // col quad: cols 4cq..4cq+3
    int g = tid >> 5;           // node group: nodes g*8..g*8+7
    int head = cq >> 4;
    int nbase = blockIdx.x * 64;
    int nvalid = min(64, NN - nbase);

    unsigned long long acc[8][2];
#pragma unroll
    for (int i = 0; i < 8; i++) { acc[i][0] = 0ull; acc[i][1] = 0ull; }

    for (int t = 0; t < TT; t++) {
        for (int c = 0; c < NCH; c++) {
            const float4* Wg4 = (const float4*)(W + (size_t)t * K * 128 + (size_t)c * KC * 128);
            for (int i = tid; i < KC * 128 / 4; i += 256)
                ((float4*)Ws)[i] = Wg4[i];
            const __half2* Ag2 = (const __half2*)(d_aggh + ((size_t)t * NN + nbase) * 2 * K);
            if (K == 64) {
                int cnt = nvalid * 32;
                for (int i = tid; i < cnt; i += 256) {
                    int node = i >> 5, j = i & 31;
                    int hh = j >> 4, pos = j & 15;
                    float2 v = __half22float2(Ag2[node * 64 + hh * 32 + c * 16 + pos]);
                    *(float2*)&As[node * NS + hh * HS + pos * 2] = v;
                }
            } else {
                int cnt = nvalid * 23;
                for (int i = tid; i < cnt; i += 256) {
                    int node = i / 23, j = i - node * 23;
                    float2 v = __half22float2(Ag2[node * 23 + j]);
                    *(float2*)&As[node * NS + j * 2] = v;
                }
            }
            __syncthreads();

#pragma unroll 4
            for (int k = 0; k < KC; k++) {
                unsigned long long w0 = *(const unsigned long long*)&Ws[k * 128 + 4 * cq];
                unsigned long long w1 = *(const unsigned long long*)&Ws[k * 128 + 4 * cq + 2];
#pragma unroll
                for (int i = 0; i < 8; i++) {
                    unsigned long long a = f32x2_bcast(As[(g * 8 + i) * NS + head * HS + k]);
                    FMA2(acc[i][0], a, w0, acc[i][0]);
                    FMA2(acc[i][1], a, w1, acc[i][1]);
                }
            }
            __syncthreads();
        }
    }

#pragma unroll
    for (int i = 0; i < 8; i++) {
        int node = g * 8 + i;
        *(float2*)&St[node * 128 + 4 * cq]     = f32x2_unpack(acc[i][0]);
        *(float2*)&St[node * 128 + 4 * cq + 2] = f32x2_unpack(acc[i][1]);
    }
    __syncthreads();

    int dd = tid & 63;
    int q = tid >> 6;   // 0..3, 16 nodes each
    float bm0 = 0.f, bm1 = 0.f;
#pragma unroll
    for (int t = 0; t < TT; t++) {
        bm0 += b[t * 128 + dd];
        bm1 += b[t * 128 + 64 + dd];
    }
    bm0 *= 0.25f; bm1 *= 0.25f;
#pragma unroll
    for (int i = 0; i < 16; i++) {
        int node = q * 16 + i;
        int n = nbase + node;
        if (n < NN) {
            float v0 = St[node * 128 + dd] * 0.25f + bm0;
            float v1 = St[node * 128 + 64 + dd] * 0.25f + bm1;
            v0 = fmaxf(v0, 0.f);
            v1 = fmaxf(v1, 0.f);
            float nrm = sqrtf(v0 * v0 + v1 * v1);
            float inv = 1.f / fmaxf(nrm, 1e-12f);
            hout[(size_t)n * 64 + dd] = 0.5f * (v0 + v1) * inv;
        }
    }
}

// ==== layer 2 collapsed: node-mean of agg + final GEMM (last-block) ====
__global__ void aggmean_final_kernel(const float* __restrict__ W2,
                                     const float* __restrict__ b2,
                                     float* __restrict__ out) {
    int t = blockIdx.y;
    int col = threadIdx.x;   // 128
    float s = 0.f;
    for (int n = blockIdx.x; n < NN; n += gridDim.x)
        s += __half2float(d_aggh[((size_t)t * NN + n) * 128 + col]);
    atomicAdd(&d_msum[t * 128 + col], s);
    __threadfence();
    __syncthreads();
    __shared__ int flag;
    if (threadIdx.x == 0) {
        int v = atomicAdd(&d_ctr, 1);
        flag = (v == (int)(gridDim.x * gridDim.y) - 1);
    }
    __syncthreads();
    if (!flag) return;
    __threadfence();

    __shared__ float sm_m[512];
    for (int i = threadIdx.x; i < 512; i += 128) sm_m[i] = d_msum[i];
    __syncthreads();
    if (threadIdx.x < 64) {
        int dd = threadIdx.x;
        float sum = 0.f;
#pragma unroll
        for (int tt = 0; tt < TT; tt++)
#pragma unroll
            for (int hh = 0; hh < 2; hh++)
                for (int k = 0; k < 64; k++)
                    sum = fmaf(sm_m[tt * 128 + hh * 64 + k],
                               W2[((size_t)(tt * 64 + k)) * 128 + hh * 64 + dd], sum);
        sum *= 0.125f / (float)NN;
        float bb = 0.f;
#pragma unroll
        for (int tt = 0; tt < TT; tt++)
            bb += b2[tt * 128 + dd] + b2[tt * 128 + 64 + dd];
        out[dd] = sum + bb * 0.125f;
    }
}

// ================= driver =================
extern "C" void kernel_launch(void* const* d_in, const int* in_sizes, int n_in,
                              void* d_out, int out_size) {
    const float* x   = (const float*)d_in[0];
    const int* edges = (const int*)  d_in[1];
    const float* W0  = (const float*)d_in[2];
    const float* al0 = (const float*)d_in[3];
    const float* ar0 = (const float*)d_in[4];
    const float* b0  = (const float*)d_in[5];
    const float* W1  = (const float*)d_in[6];
    const float* al1 = (const float*)d_in[7];
    const float* ar1 = (const float*)d_in[8];
    const float* b1  = (const float*)d_in[9];
    const float* W2  = (const float*)d_in[10];
    const float* al2 = (const float*)d_in[11];
    const float* ar2 = (const float*)d_in[12];
    const float* b2  = (const float*)d_in[13];
    float* out = (float*)d_out;

    void* hptr = nullptr;
    cudaGetSymbolAddress(&hptr, d_hbuf);
    float* h1 = (float*)hptr;
    float* h2 = h1 + (size_t)NN * 64;

    const int eg = (ETOT + 255) / 256;
    const int ng = (NN + 255) / 256;            // eler2: thread per node
    const int sg = (ROWS * 32 + 255) / 256;     // segment2: warp per row
    const int gg = (NN + 63) / 64;              // out gemm: 64-node tiles

    prep_kernel<<<256, 256>>>(W0, al0, ar0, W1, al1, ar1, W2, al2, ar2);
    hist_kernel<<<eg, 256>>>(edges);
    scan_k1<<<NBLK, 256>>>();
    scan_k3b<<<NBLK, 256>>>();
    scatter_kernel<<<eg, 256>>>(edges);

    // ---- layer 0 (K=23) ----
    eler2_kernel<23><<<ng, 256>>>(x, 0);
    segment2_kernel<23><<<sg, 256>>>(x);
    out_gemm_kernel<23><<<gg, 256>>>(W0, b0, h1);

    // ---- layer 1 (K=64) ----
    eler2_kernel<64><<<ng, 256>>>(h1, 1);
    segment2_kernel<64><<<sg, 256>>>(h1);
    out_gemm_kernel<64><<<gg, 256>>>(W1, b1, h2);

    // ---- layer 2 (K=64, collapsed output) ----
    eler2_kernel<64><<<ng, 256>>>(h2, 2);
    segment2_kernel<64><<<sg, 256>>>(h2);
    {
        dim3 ag(512, TT);
        aggmean_final_kernel<<<ag, 128>>>(W2, b2, out);
    }
}

// round 9
// speedup vs baseline: 2.8255x; 1.0001x over previous
#include <cuda_runtime.h>
#include <cuda_fp16.h>

#define NN 50000
#define EE 250000
#define TT 4
#define ROWS (TT*NN)
#define ETOT (TT*EE)
#define CHUNK 1024
#define NBLK ((ROWS + CHUNK - 1) / CHUNK)   // 196

// ---------------- scratch (static device globals) ----------------
__device__ float  d_el[ROWS * 2];
__device__ float  d_er[ROWS * 2];
__device__ float  d_wal[3 * 512];
__device__ float  d_war[3 * 512];
__device__ __half d_aggh[(size_t)ROWS * 128];   // 51.2MB, L2-resident
__device__ __half d_hbuf[2 * (size_t)NN * 64];  // fp16 activations
__device__ float  d_msum[TT * 128];
__device__ int    d_deg[ROWS];
__device__ int    d_rowptr[ROWS + 1];
__device__ int    d_cursor[ROWS];
__device__ int    d_csrc[ETOT];
__device__ int    d_bsum[NBLK];
__device__ int    d_ctr;

// ---------------- f32x2 packed helpers ----------------
__device__ __forceinline__ unsigned long long f32x2_bcast(float x) {
    unsigned long long r;
    asm("mov.b64 %0, {%1, %1};" : "=l"(r) : "f"(x));
    return r;
}
__device__ __forceinline__ float2 f32x2_unpack(unsigned long long v) {
    float2 f;
    asm("mov.b64 {%0, %1}, %2;" : "=f"(f.x), "=f"(f.y) : "l"(v));
    return f;
}
#define FMA2(d, a, b, c) \
    asm("fma.rn.f32x2 %0, %1, %2, %3;" : "=l"(d) : "l"(a), "l"(b), "l"(c))

__device__ __forceinline__ float lrelu(float x) { return x > 0.f ? x : 0.2f * x; }

// ========== prep: zero deg/msum/ctr + wal/war for all 3 layers ==========
__global__ void prep_kernel(const float* __restrict__ W0, const float* __restrict__ al0, const float* __restrict__ ar0,
                            const float* __restrict__ W1, const float* __restrict__ al1, const float* __restrict__ ar1,
                            const float* __restrict__ W2, const float* __restrict__ al2, const float* __restrict__ ar2) {
    int gi = blockIdx.x * blockDim.x + threadIdx.x;
    int stride = gridDim.x * blockDim.x;
    for (int j = gi; j < ROWS; j += stride) d_deg[j] = 0;
    if (gi < TT * 128) d_msum[gi] = 0.f;
    if (gi == 0) d_ctr = 0;

    if (blockIdx.x < 3) {
        int L = blockIdx.x;
        const float* W  = (L == 0) ? W0  : (L == 1) ? W1  : W2;
        const float* al = (L == 0) ? al0 : (L == 1) ? al1 : al2;
        const float* ar = (L == 0) ? ar0 : (L == 1) ? ar1 : ar2;
        int K = (L == 0) ? 23 : 64;
        for (int idx = threadIdx.x; idx < TT * 2 * K; idx += blockDim.x) {
            int t = idx / (2 * K);
            int rem = idx - t * 2 * K;
            int hh = rem / K;
            int k = rem - hh * K;
            float sl = 0.f, sr = 0.f;
            const float* Wr = W + ((size_t)(t * K + k)) * 128 + hh * 64;
            const float* alr = al + (t * 2 + hh) * 64;
            const float* arr = ar + (t * 2 + hh) * 64;
#pragma unroll
            for (int j = 0; j < 64; j++) {
                float w = Wr[j];
                sl = fmaf(w, alr[j], sl);
                sr = fmaf(w, arr[j], sr);
            }
            d_wal[L * 512 + (t * 2 + hh) * 64 + k] = sl;
            d_war[L * 512 + (t * 2 + hh) * 64 + k] = sr;
        }
    }
}

// ================= CSR build =================
__global__ void hist_kernel(const int* __restrict__ edges) {
    int i = blockIdx.x * blockDim.x + threadIdx.x;
    if (i >= ETOT) return;
    int t = i / EE, e = i - t * EE;
    int d = edges[(size_t)t * 2 * EE + EE + e];
    atomicAdd(&d_deg[t * NN + d], 1);
}

__global__ void scan_k1() {
    __shared__ int sm[256];
    int b = blockIdx.x, tid = threadIdx.x;
    int s = 0;
#pragma unroll
    for (int i = 0; i < 4; i++) {
        int idx = b * CHUNK + tid + 256 * i;
        if (idx < ROWS) s += d_deg[idx];
    }
    sm[tid] = s;
    __syncthreads();
    for (int o = 128; o > 0; o >>= 1) {
        if (tid < o) sm[tid] += sm[tid + o];
        __syncthreads();
    }
    if (tid == 0) d_bsum[b] = sm[0];
}

__global__ void scan_k3b() {
    __shared__ int sp[256];
    __shared__ int sm[256];
    int b = blockIdx.x, tid = threadIdx.x;
    int v = (tid < b) ? d_bsum[tid] : 0;
    sp[tid] = v;
    __syncthreads();
    for (int o = 128; o > 0; o >>= 1) {
        if (tid < o) sp[tid] += sp[tid + o];
        __syncthreads();
    }
    int pre = sp[0];

    int base = b * CHUNK + tid * 4;
    int vv[4], p[4], s = 0;
#pragma unroll
    for (int i = 0; i < 4; i++) {
        int idx = base + i;
        vv[i] = (idx < ROWS) ? d_deg[idx] : 0;
        p[i] = s;
        s += vv[i];
    }
    sm[tid] = s;
    __syncthreads();
    for (int o = 1; o < 256; o <<= 1) {
        int add = (tid >= o) ? sm[tid - o] : 0;
        __syncthreads();
        sm[tid] += add;
        __syncthreads();
    }
    int off = pre + (tid ? sm[tid - 1] : 0);
#pragma unroll
    for (int i = 0; i < 4; i++) {
        int idx = base + i;
        if (idx < ROWS) {
            d_rowptr[idx] = off + p[i];
            d_cursor[idx] = off + p[i];
        }
    }
    if (b == 0 && tid == 0) d_rowptr[ROWS] = ETOT;
}

__global__ void scatter_kernel(const int* __restrict__ edges) {
    int i = blockIdx.x * blockDim.x + threadIdx.x;
    if (i >= ETOT) return;
    int t = i / EE, e = i - t * EE;
    int s = edges[(size_t)t * 2 * EE + e];
    int d = edges[(size_t)t * 2 * EE + EE + e];
    int pos = atomicAdd(&d_cursor[t * NN + d], 1);
    d_csrc[pos] = s;
}

// ================= eler =================
// layer 0: thread-per-node on fp32 x (K=23)
__global__ void eler23_kernel(const float* __restrict__ x) {
    __shared__ float swal[512], swar[512];
    int tid = threadIdx.x;
    swal[tid] = d_wal[tid];       swal[tid + 256] = d_wal[tid + 256];
    swar[tid] = d_war[tid];       swar[tid + 256] = d_war[tid + 256];
    __syncthreads();
    int n = blockIdx.x * blockDim.x + tid;
    if (n >= NN) return;
    float hreg[23];
#pragma unroll
    for (int i = 0; i < 23; i++) hreg[i] = x[(size_t)n * 23 + i];
#pragma unroll
    for (int t = 0; t < TT; t++) {
        float pl0 = 0.f, pl1 = 0.f, pr0 = 0.f, pr1 = 0.f;
        int b0 = (t * 2) * 64, b1 = (t * 2 + 1) * 64;
#pragma unroll
        for (int k = 0; k < 23; k++) {
            float hk = hreg[k];
            pl0 = fmaf(hk, swal[b0 + k], pl0);
            pl1 = fmaf(hk, swal[b1 + k], pl1);
            pr0 = fmaf(hk, swar[b0 + k], pr0);
            pr1 = fmaf(hk, swar[b1 + k], pr1);
        }
        *(float2*)&d_el[((size_t)t * NN + n) * 2] = make_float2(pl0, pl1);
        *(float2*)&d_er[((size_t)t * NN + n) * 2] = make_float2(pr0, pr1);
    }
}

// layers 1,2: thread-per-node on fp16 h
__global__ void eler64_kernel(const __half* __restrict__ h, int layer) {
    __shared__ float swal[512], swar[512];
    int tid = threadIdx.x;
    swal[tid] = d_wal[layer * 512 + tid];
    swal[tid + 256] = d_wal[layer * 512 + tid + 256];
    swar[tid] = d_war[layer * 512 + tid];
    swar[tid + 256] = d_war[layer * 512 + tid + 256];
    __syncthreads();
    int n = blockIdx.x * blockDim.x + tid;
    if (n >= NN) return;
    float hreg[64];
    const __half2* hr = (const __half2*)(h + (size_t)n * 64);
#pragma unroll
    for (int i = 0; i < 32; i++) {
        float2 v = __half22float2(hr[i]);
        hreg[2 * i] = v.x;
        hreg[2 * i + 1] = v.y;
    }
#pragma unroll
    for (int t = 0; t < TT; t++) {
        float pl0 = 0.f, pl1 = 0.f, pr0 = 0.f, pr1 = 0.f;
        int b0 = (t * 2) * 64, b1 = (t * 2 + 1) * 64;
#pragma unroll
        for (int k = 0; k < 64; k++) {
            float hk = hreg[k];
            pl0 = fmaf(hk, swal[b0 + k], pl0);
            pl1 = fmaf(hk, swal[b1 + k], pl1);
            pr0 = fmaf(hk, swar[b0 + k], pr0);
            pr1 = fmaf(hk, swar[b1 + k], pr1);
        }
        *(float2*)&d_el[((size_t)t * NN + n) * 2] = make_float2(pl0, pl1);
        *(float2*)&d_er[((size_t)t * NN + n) * 2] = make_float2(pr0, pr1);
    }
}

// ================= segment =================
// layer 0 (fp32 x, K=23): agg stored per-head padded to 24 (stride 48)
__global__ void segment23_kernel(const float* __restrict__ x) {
    int tid = threadIdx.x;
    int lane = tid & 31;
    int row = (blockIdx.x * blockDim.x + tid) >> 5;   // t*NN + d
    if (row >= ROWS) return;
    int t = row / NN;
    const float* elb = d_el + (size_t)t * NN * 2;
    int beg = d_rowptr[row], end = d_rowptr[row + 1];
    float2 er2 = *(const float2*)&d_er[(size_t)row * 2];

    float den0 = 0.f, den1 = 0.f;
    float as0 = 0.f, as1 = 0.f;

    for (int j = beg; j < end; j += 2) {
        int sA = d_csrc[j];
        bool hasB = (j + 1 < end);
        int sB = hasB ? d_csrc[j + 1] : sA;
        float2 elA = *(const float2*)&elb[(size_t)sA * 2];
        float2 elB = *(const float2*)&elb[(size_t)sB * 2];
        float wA0 = __expf(lrelu(elA.x + er2.x));
        float wA1 = __expf(lrelu(elA.y + er2.y));
        float wB0 = hasB ? __expf(lrelu(elB.x + er2.x)) : 0.f;
        float wB1 = hasB ? __expf(lrelu(elB.y + er2.y)) : 0.f;
        den0 += wA0 + wB0;
        den1 += wA1 + wB1;
        float hA = (lane < 23) ? x[(size_t)sA * 23 + lane] : 0.f;
        float hB = (lane < 23) ? x[(size_t)sB * 23 + lane] : 0.f;
        as0 = fmaf(wA0, hA, fmaf(wB0, hB, as0));
        as1 = fmaf(wA1, hA, fmaf(wB1, hB, as1));
    }
    float inv0 = (end > beg) ? 1.f / den0 : 0.f;
    float inv1 = (end > beg) ? 1.f / den1 : 0.f;
    size_t base = (size_t)row * 48;
    if (lane < 23) {
        d_aggh[base + lane]      = __float2half(as0 * inv0);
        d_aggh[base + 24 + lane] = __float2half(as1 * inv1);
    } else if (lane == 23) {
        d_aggh[base + 23] = __float2half(0.f);
        d_aggh[base + 47] = __float2half(0.f);
    }
}

// layers 1,2 (fp16 h, K=64): agg stride 128, 2-wide unrolled loop
__global__ void segment64_kernel(const __half* __restrict__ h) {
    int tid = threadIdx.x;
    int lane = tid & 31;
    int row = (blockIdx.x * blockDim.x + tid) >> 5;   // t*NN + d
    if (row >= ROWS) return;
    int t = row / NN;
    const float* elb = d_el + (size_t)t * NN * 2;
    const __half2* h2p = (const __half2*)h;
    int beg = d_rowptr[row], end = d_rowptr[row + 1];
    float2 er2 = *(const float2*)&d_er[(size_t)row * 2];

    float den0 = 0.f, den1 = 0.f;
    float2 a0 = make_float2(0.f, 0.f), a1 = make_float2(0.f, 0.f);

    for (int j = beg; j < end; j += 2) {
        int sA = d_csrc[j];
        bool hasB = (j + 1 < end);
        int sB = hasB ? d_csrc[j + 1] : sA;
        float2 elA = *(const float2*)&elb[(size_t)sA * 2];
        float2 elB = *(const float2*)&elb[(size_t)sB * 2];
        float wA0 = __expf(lrelu(elA.x + er2.x));
        float wA1 = __expf(lrelu(elA.y + er2.y));
        float wB0 = hasB ? __expf(lrelu(elB.x + er2.x)) : 0.f;
        float wB1 = hasB ? __expf(lrelu(elB.y + er2.y)) : 0.f;
        den0 += wA0 + wB0;
        den1 += wA1 + wB1;
        float2 hA = __half22float2(h2p[(size_t)sA * 32 + lane]);
        float2 hB = __half22float2(h2p[(size_t)sB * 32 + lane]);
        a0.x = fmaf(wA0, hA.x, fmaf(wB0, hB.x, a0.x));
        a0.y = fmaf(wA0, hA.y, fmaf(wB0, hB.y, a0.y));
        a1.x = fmaf(wA1, hA.x, fmaf(wB1, hB.x, a1.x));
        a1.y = fmaf(wA1, hA.y, fmaf(wB1, hB.y, a1.y));
    }
    float inv0 = (end > beg) ? 1.f / den0 : 0.f;
    float inv1 = (end > beg) ? 1.f / den1 : 0.f;
    __half2* p = (__half2*)&d_aggh[(size_t)row * 128];
    p[lane]      = __floats2half2_rn(a0.x * inv0, a0.y * inv0);
    p[32 + lane] = __floats2half2_rn(a1.x * inv1, a1.y * inv1);
}

// ===== out gemm 64: k4-blocked inner loop (float4 A broadcast per 4k) =====
__global__ void out_gemm64_kernel(const float* __restrict__ W,
                                  const float* __restrict__ b,
                                  __half* __restrict__ hout) {
    constexpr int KC = 32, NS = 72, HS = 36;
    __shared__ __align__(16) char sbuf[34816];
    float* Ws = (float*)sbuf;                       // 32*128 floats
    float* As = (float*)(sbuf + KC * 128 * 4);      // 64*72 floats
    float* St = (float*)sbuf;                       // 64*128 floats (aliased)

    int tid = threadIdx.x;
    int cq = tid & 31;          // col quad: cols 4cq..4cq+3
    int g = tid >> 5;           // node group: nodes g*8..g*8+7
    int head = cq >> 4;
    int nbase = blockIdx.x * 64;
    int nvalid = min(64, NN - nbase);

    unsigned long long acc[8][2];
#pragma unroll
    for (int i = 0; i < 8; i++) { acc[i][0] = 0ull; acc[i][1] = 0ull; }

    for (int t = 0; t < TT; t++) {
        for (int c = 0; c < 2; c++) {
            const float4* Wg4 = (const float4*)(W + (size_t)t * 64 * 128 + (size_t)c * KC * 128);
            for (int i = tid; i < KC * 128 / 4; i += 256)
                ((float4*)Ws)[i] = Wg4[i];
            const __half2* Ag2 = (const __half2*)(d_aggh + ((size_t)t * NN + nbase) * 128);
            int cnt = nvalid * 32;
            for (int i = tid; i < cnt; i += 256) {
                int node = i >> 5, j = i & 31;
                int hh = j >> 4, pos = j & 15;
                float2 v = __half22float2(Ag2[node * 64 + hh * 32 + c * 16 + pos]);
                *(float2*)&As[node * NS + hh * HS + pos * 2] = v;
            }
            __syncthreads();

#pragma unroll
            for (int k4 = 0; k4 < KC; k4 += 4) {
                unsigned long long w0[4], w1[4];
#pragma unroll
                for (int kk = 0; kk < 4; kk++) {
                    w0[kk] = *(const unsigned long long*)&Ws[(k4 + kk) * 128 + 4 * cq];
                    w1[kk] = *(const unsigned long long*)&Ws[(k4 + kk) * 128 + 4 * cq + 2];
                }
#pragma unroll
                for (int i = 0; i < 8; i++) {
                    float4 a4 = *(const float4*)&As[(g * 8 + i) * NS + head * HS + k4];
                    unsigned long long ax = f32x2_bcast(a4.x);
                    unsigned long long ay = f32x2_bcast(a4.y);
                    unsigned long long az = f32x2_bcast(a4.z);
                    unsigned long long aw = f32x2_bcast(a4.w);
                    FMA2(acc[i][0], ax, w0[0], acc[i][0]);
                    FMA2(acc[i][1], ax, w1[0], acc[i][1]);
                    FMA2(acc[i][0], ay, w0[1], acc[i][0]);
                    FMA2(acc[i][1], ay, w1[1], acc[i][1]);
                    FMA2(acc[i][0], az, w0[2], acc[i][0]);
                    FMA2(acc[i][1], az, w1[2], acc[i][1]);
                    FMA2(acc[i][0], aw, w0[3], acc[i][0]);
                    FMA2(acc[i][1], aw, w1[3], acc[i][1]);
                }
            }
            __syncthreads();
        }
    }

#pragma unroll
    for (int i = 0; i < 8; i++) {
        int node = g * 8 + i;
        *(float2*)&St[node * 128 + 4 * cq]     = f32x2_unpack(acc[i][0]);
        *(float2*)&St[node * 128 + 4 * cq + 2] = f32x2_unpack(acc[i][1]);
    }
    __syncthreads();

    int dd = tid & 63;
    int q = tid >> 6;
    float bm0 = 0.f, bm1 = 0.f;
#pragma unroll
    for (int t = 0; t < TT; t++) {
        bm0 += b[t * 128 + dd];
        bm1 += b[t * 128 + 64 + dd];
    }
    bm0 *= 0.25f; bm1 *= 0.25f;
#pragma unroll
    for (int i = 0; i < 16; i++) {
        int node = q * 16 + i;
        int n = nbase + node;
        if (n < NN) {
            float v0 = St[node * 128 + dd] * 0.25f + bm0;
            float v1 = St[node * 128 + 64 + dd] * 0.25f + bm1;
            v0 = fmaxf(v0, 0.f);
            v1 = fmaxf(v1, 0.f);
            float nrm = sqrtf(v0 * v0 + v1 * v1);
            float inv = 1.f / fmaxf(nrm, 1e-12f);
            hout[(size_t)n * 64 + dd] = __float2half(0.5f * (v0 + v1) * inv);
        }
    }
}

// ===== out gemm layer0: K padded to 24, agg stride 48 (per-head pad) =====
__global__ void out_gemm23_kernel(const float* __restrict__ W,
                                  const float* __restrict__ b,
                                  __half* __restrict__ hout) {
    constexpr int NS = 48, HS = 24;
    __shared__ __align__(16) char sbuf[34816];
    float* Ws = (float*)sbuf;                   // 24*128 floats (row 23 zero)
    float* As = (float*)(sbuf + 24 * 128 * 4);  // 64*48 floats
    float* St = (float*)sbuf;                   // 64*128 floats (aliased)

    int tid = threadIdx.x;
    int cq = tid & 31;
    int g = tid >> 5;
    int head = cq >> 4;
    int nbase = blockIdx.x * 64;
    int nvalid = min(64, NN - nbase);

    unsigned long long acc[8][2];
#pragma unroll
    for (int i = 0; i < 8; i++) { acc[i][0] = 0ull; acc[i][1] = 0ull; }

    for (int t = 0; t < TT; t++) {
        const float4* Wg4 = (const float4*)(W + (size_t)t * 23 * 128);
        for (int i = tid; i < 24 * 32; i += 256)
            ((float4*)Ws)[i] = (i < 23 * 32) ? Wg4[i] : make_float4(0.f, 0.f, 0.f, 0.f);
        const __half2* Ag2 = (const __half2*)(d_aggh + ((size_t)t * NN + nbase) * 48);
        int cnt = nvalid * 24;   // half2 units per node = 24 (covers 48 halves incl pads)
        for (int i = tid; i < cnt; i += 256) {
            int node = i / 24, j = i - node * 24;
            float2 v = __half22float2(Ag2[node * 24 + j]);
            *(float2*)&As[node * NS + j * 2] = v;
        }
        __syncthreads();

#pragma unroll
        for (int k4 = 0; k4 < 24; k4 += 4) {
            unsigned long long w0[4], w1[4];
#pragma unroll
            for (int kk = 0; kk < 4; kk++) {
                w0[kk] = *(const unsigned long long*)&Ws[(k4 + kk) * 128 + 4 * cq];
                w1[kk] = *(const unsigned long long*)&Ws[(k4 + kk) * 128 + 4 * cq + 2];
            }
#pragma unroll
            for (int i = 0; i < 8; i++) {
                float4 a4 = *(const float4*)&As[(g * 8 + i) * NS + head * HS + k4];
                unsigned long long ax = f32x2_bcast(a4.x);
                unsigned long long ay = f32x2_bcast(a4.y);
                unsigned long long az = f32x2_bcast(a4.z);
                unsigned long long aw = f32x2_bcast(a4.w);
                FMA2(acc[i][0], ax, w0[0], acc[i][0]);
                FMA2(acc[i][1], ax, w1[0], acc[i][1]);
                FMA2(acc[i][0], ay, w0[1], acc[i][0]);
                FMA2(acc[i][1], ay, w1[1], acc[i][1]);
                FMA2(acc[i][0], az, w0[2], acc[i][0]);
                FMA2(acc[i][1], az, w1[2], acc[i][1]);
                FMA2(acc[i][0], aw, w0[3], acc[i][0]);
                FMA2(acc[i][1], aw, w1[3], acc[i][1]);
            }
        }
        __syncthreads();
    }

#pragma unroll
    for (int i = 0; i < 8; i++) {
        int node = g * 8 + i;
        *(float2*)&St[node * 128 + 4 * cq]     = f32x2_unpack(acc[i][0]);
        *(float2*)&St[node * 128 + 4 * cq + 2] = f32x2_unpack(acc[i][1]);
    }
    __syncthreads();

    int dd = tid & 63;
    int q = tid >> 6;
    float bm0 = 0.f, bm1 = 0.f;
#pragma unroll
    for (int t = 0; t < TT; t++) {
        bm0 += b[t * 128 + dd];
        bm1 += b[t * 128 + 64 + dd];
    }
    bm0 *= 0.25f; bm1 *= 0.25f;
#pragma unroll
    for (int i = 0; i < 16; i++) {
        int node = q * 16 + i;
        int n = nbase + node;
        if (n < NN) {
            float v0 = St[node * 128 + dd] * 0.25f + bm0;
            float v1 = St[node * 128 + 64 + dd] * 0.25f + bm1;
            v0 = fmaxf(v0, 0.f);
            v1 = fmaxf(v1, 0.f);
            float nrm = sqrtf(v0 * v0 + v1 * v1);
            float inv = 1.f / fmaxf(nrm, 1e-12f);
            hout[(size_t)n * 64 + dd] = __float2half(0.5f * (v0 + v1) * inv);
        }
    }
}

// ==== layer 2 collapsed: node-mean of agg + final GEMM (last-block) ====
__global__ void aggmean_final_kernel(const float* __restrict__ W2,
                                     const float* __restrict__ b2,
                                     float* __restrict__ out) {
    int t = blockIdx.y;
    int col = threadIdx.x;   // 128
    float s = 0.f;
    for (int n = blockIdx.x; n < NN; n += gridDim.x)
        s += __half2float(d_aggh[((size_t)t * NN + n) * 128 + col]);
    atomicAdd(&d_msum[t * 128 + col], s);
    __threadfence();
    __syncthreads();
    __shared__ int flag;
    if (threadIdx.x == 0) {
        int v = atomicAdd(&d_ctr, 1);
        flag = (v == (int)(gridDim.x * gridDim.y) - 1);
    }
    __syncthreads();
    if (!flag) return;
    __threadfence();

    __shared__ float sm_m[512];
    for (int i = threadIdx.x; i < 512; i += 128) sm_m[i] = d_msum[i];
    __syncthreads();
    if (threadIdx.x < 64) {
        int dd = threadIdx.x;
        float sum = 0.f;
#pragma unroll
        for (int tt = 0; tt < TT; tt++)
#pragma unroll
            for (int hh = 0; hh < 2; hh++)
                for (int k = 0; k < 64; k++)
                    sum = fmaf(sm_m[tt * 128 + hh * 64 + k],
                               W2[((size_t)(tt * 64 + k)) * 128 + hh * 64 + dd], sum);
        sum *= 0.125f / (float)NN;
        float bb = 0.f;
#pragma unroll
        for (int tt = 0; tt < TT; tt++)
            bb += b2[tt * 128 + dd] + b2[tt * 128 + 64 + dd];
        out[dd] = sum + bb * 0.125f;
    }
}

// ================= driver =================
extern "C" void kernel_launch(void* const* d_in, const int* in_sizes, int n_in,
                              void* d_out, int out_size) {
    const float* x   = (const float*)d_in[0];
    const int* edges = (const int*)  d_in[1];
    const float* W0  = (const float*)d_in[2];
    const float* al0 = (const float*)d_in[3];
    const float* ar0 = (const float*)d_in[4];
    const float* b0  = (const float*)d_in[5];
    const float* W1  = (const float*)d_in[6];
    const float* al1 = (const float*)d_in[7];
    const float* ar1 = (const float*)d_in[8];
    const float* b1  = (const float*)d_in[9];
    const float* W2  = (const float*)d_in[10];
    const float* al2 = (const float*)d_in[11];
    const float* ar2 = (const float*)d_in[12];
    const float* b2  = (const float*)d_in[13];
    float* out = (float*)d_out;

    void* hptr = nullptr;
    cudaGetSymbolAddress(&hptr, d_hbuf);
    __half* h1 = (__half*)hptr;
    __half* h2 = h1 + (size_t)NN * 64;

    const int eg = (ETOT + 255) / 256;
    const int ng = (NN + 255) / 256;            // eler: thread per node
    const int sg = (ROWS * 32 + 255) / 256;     // segment: warp per row
    const int gg = (NN + 63) / 64;              // out gemm: 64-node tiles

    prep_kernel<<<256, 256>>>(W0, al0, ar0, W1, al1, ar1, W2, al2, ar2);
    hist_kernel<<<eg, 256>>>(edges);
    scan_k1<<<NBLK, 256>>>();
    scan_k3b<<<NBLK, 256>>>();
    scatter_kernel<<<eg, 256>>>(edges);

    // ---- layer 0 (K=23) ----
    eler23_kernel<<<ng, 256>>>(x);
    segment23_kernel<<<sg, 256>>>(x);
    out_gemm23_kernel<<<gg, 256>>>(W0, b0, h1);

    // ---- layer 1 (K=64) ----
    eler64_kernel<<<ng, 256>>>(h1, 1);
    segment64_kernel<<<sg, 256>>>(h1);
    out_gemm64_kernel<<<gg, 256>>>(W1, b1, h2);

    // ---- layer 2 (K=64, collapsed output) ----
    eler64_kernel<<<ng, 256>>>(h2, 2);
    segment64_kernel<<<sg, 256>>>(h2);
    {
        dim3 ag(512, TT);
        aggmean_final_kernel<<<ag, 128>>>(W2, b2, out);
    }
}

// round 10
// speedup vs baseline: 3.4457x; 1.2195x over previous
#include <cuda_runtime.h>
#include <cuda_fp16.h>

#define NN 50000
#define EE 250000
#define TT 4
#define ROWS (TT*NN)
#define ETOT (TT*EE)
#define CHUNK 1024
#define NBLK ((ROWS + CHUNK - 1) / CHUNK)   // 196

// ---------------- scratch (static device globals) ----------------
__device__ float  d_el[ROWS * 2];
__device__ float  d_er[ROWS * 2];
__device__ float  d_wal[3 * 512];
__device__ float  d_war[3 * 512];
__device__ __half d_aggh[(size_t)ROWS * 128];   // 51.2MB, L2-resident
__device__ __half d_hbuf[2 * (size_t)NN * 64];  // fp16 activations
__device__ __half d_wt0[TT * 128 * 24];         // W0^T fp16 [t][n][k], k-pad 24
__device__ __half d_wt1[TT * 128 * 64];         // W1^T fp16 [t][n][k]
__device__ float  d_msum[TT * 128];
__device__ int    d_deg[ROWS];
__device__ int    d_rowptr[ROWS + 1];
__device__ int    d_cursor[ROWS];
__device__ int    d_csrc[ETOT];
__device__ int    d_bsum[NBLK];
__device__ int    d_ctr;

__device__ __forceinline__ float lrelu(float x) { return x > 0.f ? x : 0.2f * x; }

#define MMA16816(d, a, b0_, b1_) \
    asm volatile("mma.sync.aligned.m16n8k16.row.col.f32.f16.f16.f32 " \
        "{%0,%1,%2,%3}, {%4,%5,%6,%7}, {%8,%9}, {%0,%1,%2,%3};" \
        : "+f"((d)[0]), "+f"((d)[1]), "+f"((d)[2]), "+f"((d)[3]) \
        : "r"((a)[0]), "r"((a)[1]), "r"((a)[2]), "r"((a)[3]), \
          "r"(b0_), "r"(b1_))

// ========== prep: zero deg/msum/ctr + wal/war + fp16 W transposes ==========
__global__ void prep_kernel(const float* __restrict__ W0, const float* __restrict__ al0, const float* __restrict__ ar0,
                            const float* __restrict__ W1, const float* __restrict__ al1, const float* __restrict__ ar1,
                            const float* __restrict__ W2, const float* __restrict__ al2, const float* __restrict__ ar2) {
    int gi = blockIdx.x * blockDim.x + threadIdx.x;
    int stride = gridDim.x * blockDim.x;
    for (int j = gi; j < ROWS; j += stride) d_deg[j] = 0;
    if (gi < TT * 128) d_msum[gi] = 0.f;
    if (gi == 0) d_ctr = 0;

    // W0^T fp16 (k padded to 24 with zeros)
    for (int i = gi; i < TT * 128 * 24; i += stride) {
        int t = i / (128 * 24);
        int r = i - t * 128 * 24;
        int n = r / 24, k = r - n * 24;
        float v = (k < 23) ? W0[((size_t)(t * 23 + k)) * 128 + n] : 0.f;
        d_wt0[i] = __float2half(v);
    }
    // W1^T fp16
    for (int i = gi; i < TT * 128 * 64; i += stride) {
        int t = i / (128 * 64);
        int r = i - t * 128 * 64;
        int n = r / 64, k = r - n * 64;
        d_wt1[i] = __float2half(W1[((size_t)(t * 64 + k)) * 128 + n]);
    }

    if (blockIdx.x < 3) {
        int L = blockIdx.x;
        const float* W  = (L == 0) ? W0  : (L == 1) ? W1  : W2;
        const float* al = (L == 0) ? al0 : (L == 1) ? al1 : al2;
        const float* ar = (L == 0) ? ar0 : (L == 1) ? ar1 : ar2;
        int K = (L == 0) ? 23 : 64;
        for (int idx = threadIdx.x; idx < TT * 2 * K; idx += blockDim.x) {
            int t = idx / (2 * K);
            int rem = idx - t * 2 * K;
            int hh = rem / K;
            int k = rem - hh * K;
            float sl = 0.f, sr = 0.f;
            const float* Wr = W + ((size_t)(t * K + k)) * 128 + hh * 64;
            const float* alr = al + (t * 2 + hh) * 64;
            const float* arr = ar + (t * 2 + hh) * 64;
#pragma unroll
            for (int j = 0; j < 64; j++) {
                float w = Wr[j];
                sl = fmaf(w, alr[j], sl);
                sr = fmaf(w, arr[j], sr);
            }
            d_wal[L * 512 + (t * 2 + hh) * 64 + k] = sl;
            d_war[L * 512 + (t * 2 + hh) * 64 + k] = sr;
        }
    }
}

// ================= CSR build =================
__global__ void hist_kernel(const int* __restrict__ edges) {
    int i = blockIdx.x * blockDim.x + threadIdx.x;
    if (i >= ETOT) return;
    int t = i / EE, e = i - t * EE;
    int d = edges[(size_t)t * 2 * EE + EE + e];
    atomicAdd(&d_deg[t * NN + d], 1);
}

__global__ void scan_k1() {
    __shared__ int sm[256];
    int b = blockIdx.x, tid = threadIdx.x;
    int s = 0;
#pragma unroll
    for (int i = 0; i < 4; i++) {
        int idx = b * CHUNK + tid + 256 * i;
        if (idx < ROWS) s += d_deg[idx];
    }
    sm[tid] = s;
    __syncthreads();
    for (int o = 128; o > 0; o >>= 1) {
        if (tid < o) sm[tid] += sm[tid + o];
        __syncthreads();
    }
    if (tid == 0) d_bsum[b] = sm[0];
}

__global__ void scan_k3b() {
    __shared__ int sp[256];
    __shared__ int sm[256];
    int b = blockIdx.x, tid = threadIdx.x;
    int v = (tid < b) ? d_bsum[tid] : 0;
    sp[tid] = v;
    __syncthreads();
    for (int o = 128; o > 0; o >>= 1) {
        if (tid < o) sp[tid] += sp[tid + o];
        __syncthreads();
    }
    int pre = sp[0];

    int base = b * CHUNK + tid * 4;
    int vv[4], p[4], s = 0;
#pragma unroll
    for (int i = 0; i < 4; i++) {
        int idx = base + i;
        vv[i] = (idx < ROWS) ? d_deg[idx] : 0;
        p[i] = s;
        s += vv[i];
    }
    sm[tid] = s;
    __syncthreads();
    for (int o = 1; o < 256; o <<= 1) {
        int add = (tid >= o) ? sm[tid - o] : 0;
        __syncthreads();
        sm[tid] += add;
        __syncthreads();
    }
    int off = pre + (tid ? sm[tid - 1] : 0);
#pragma unroll
    for (int i = 0; i < 4; i++) {
        int idx = base + i;
        if (idx < ROWS) {
            d_rowptr[idx] = off + p[i];
            d_cursor[idx] = off + p[i];
        }
    }
    if (b == 0 && tid == 0) d_rowptr[ROWS] = ETOT;
}

__global__ void scatter_kernel(const int* __restrict__ edges) {
    int i = blockIdx.x * blockDim.x + threadIdx.x;
    if (i >= ETOT) return;
    int t = i / EE, e = i - t * EE;
    int s = edges[(size_t)t * 2 * EE + e];
    int d = edges[(size_t)t * 2 * EE + EE + e];
    int pos = atomicAdd(&d_cursor[t * NN + d], 1);
    d_csrc[pos] = s;
}

// ================= eler =================
__global__ void eler23_kernel(const float* __restrict__ x) {
    __shared__ float swal[512], swar[512];
    int tid = threadIdx.x;
    swal[tid] = d_wal[tid];       swal[tid + 256] = d_wal[tid + 256];
    swar[tid] = d_war[tid];       swar[tid + 256] = d_war[tid + 256];
    __syncthreads();
    int n = blockIdx.x * blockDim.x + tid;
    if (n >= NN) return;
    float hreg[23];
#pragma unroll
    for (int i = 0; i < 23; i++) hreg[i] = x[(size_t)n * 23 + i];
#pragma unroll
    for (int t = 0; t < TT; t++) {
        float pl0 = 0.f, pl1 = 0.f, pr0 = 0.f, pr1 = 0.f;
        int b0 = (t * 2) * 64, b1 = (t * 2 + 1) * 64;
#pragma unroll
        for (int k = 0; k < 23; k++) {
            float hk = hreg[k];
            pl0 = fmaf(hk, swal[b0 + k], pl0);
            pl1 = fmaf(hk, swal[b1 + k], pl1);
            pr0 = fmaf(hk, swar[b0 + k], pr0);
            pr1 = fmaf(hk, swar[b1 + k], pr1);
        }
        *(float2*)&d_el[((size_t)t * NN + n) * 2] = make_float2(pl0, pl1);
        *(float2*)&d_er[((size_t)t * NN + n) * 2] = make_float2(pr0, pr1);
    }
}

__global__ void eler64_kernel(const __half* __restrict__ h, int layer) {
    __shared__ float swal[512], swar[512];
    int tid = threadIdx.x;
    swal[tid] = d_wal[layer * 512 + tid];
    swal[tid + 256] = d_wal[layer * 512 + tid + 256];
    swar[tid] = d_war[layer * 512 + tid];
    swar[tid + 256] = d_war[layer * 512 + tid + 256];
    __syncthreads();
    int n = blockIdx.x * blockDim.x + tid;
    if (n >= NN) return;
    float hreg[64];
    const __half2* hr = (const __half2*)(h + (size_t)n * 64);
#pragma unroll
    for (int i = 0; i < 32; i++) {
        float2 v = __half22float2(hr[i]);
        hreg[2 * i] = v.x;
        hreg[2 * i + 1] = v.y;
    }
#pragma unroll
    for (int t = 0; t < TT; t++) {
        float pl0 = 0.f, pl1 = 0.f, pr0 = 0.f, pr1 = 0.f;
        int b0 = (t * 2) * 64, b1 = (t * 2 + 1) * 64;
#pragma unroll
        for (int k = 0; k < 64; k++) {
            float hk = hreg[k];
            pl0 = fmaf(hk, swal[b0 + k], pl0);
            pl1 = fmaf(hk, swal[b1 + k], pl1);
            pr0 = fmaf(hk, swar[b0 + k], pr0);
            pr1 = fmaf(hk, swar[b1 + k], pr1);
        }
        *(float2*)&d_el[((size_t)t * NN + n) * 2] = make_float2(pl0, pl1);
        *(float2*)&d_er[((size_t)t * NN + n) * 2] = make_float2(pr0, pr1);
    }
}

// ================= segment =================
// layer 0 (fp32 x, K=23): agg per-head padded to 24 (row stride 48)
__global__ void segment23_kernel(const float* __restrict__ x) {
    int tid = threadIdx.x;
    int lane = tid & 31;
    int row = (blockIdx.x * blockDim.x + tid) >> 5;
    if (row >= ROWS) return;
    int t = row / NN;
    const float* elb = d_el + (size_t)t * NN * 2;
    int beg = d_rowptr[row], end = d_rowptr[row + 1];
    float2 er2 = *(const float2*)&d_er[(size_t)row * 2];

    float den0 = 0.f, den1 = 0.f;
    float as0 = 0.f, as1 = 0.f;

    for (int j = beg; j < end; j += 2) {
        int sA = d_csrc[j];
        bool hasB = (j + 1 < end);
        int sB = hasB ? d_csrc[j + 1] : sA;
        float2 elA = *(const float2*)&elb[(size_t)sA * 2];
        float2 elB = *(const float2*)&elb[(size_t)sB * 2];
        float wA0 = __expf(lrelu(elA.x + er2.x));
        float wA1 = __expf(lrelu(elA.y + er2.y));
        float wB0 = hasB ? __expf(lrelu(elB.x + er2.x)) : 0.f;
        float wB1 = hasB ? __expf(lrelu(elB.y + er2.y)) : 0.f;
        den0 += wA0 + wB0;
        den1 += wA1 + wB1;
        float hA = (lane < 23) ? x[(size_t)sA * 23 + lane] : 0.f;
        float hB = (lane < 23) ? x[(size_t)sB * 23 + lane] : 0.f;
        as0 = fmaf(wA0, hA, fmaf(wB0, hB, as0));
        as1 = fmaf(wA1, hA, fmaf(wB1, hB, as1));
    }
    float inv0 = (end > beg) ? 1.f / den0 : 0.f;
    float inv1 = (end > beg) ? 1.f / den1 : 0.f;
    size_t base = (size_t)row * 48;
    if (lane < 23) {
        d_aggh[base + lane]      = __float2half(as0 * inv0);
        d_aggh[base + 24 + lane] = __float2half(as1 * inv1);
    } else if (lane == 23) {
        d_aggh[base + 23] = __float2half(0.f);
        d_aggh[base + 47] = __float2half(0.f);
    }
}

// layers 1,2 (fp16 h, K=64): agg stride 128
__global__ void segment64_kernel(const __half* __restrict__ h) {
    int tid = threadIdx.x;
    int lane = tid & 31;
    int row = (blockIdx.x * blockDim.x + tid) >> 5;
    if (row >= ROWS) return;
    int t = row / NN;
    const float* elb = d_el + (size_t)t * NN * 2;
    const __half2* h2p = (const __half2*)h;
    int beg = d_rowptr[row], end = d_rowptr[row + 1];
    float2 er2 = *(const float2*)&d_er[(size_t)row * 2];

    float den0 = 0.f, den1 = 0.f;
    float2 a0 = make_float2(0.f, 0.f), a1 = make_float2(0.f, 0.f);

    for (int j = beg; j < end; j += 2) {
        int sA = d_csrc[j];
        bool hasB = (j + 1 < end);
        int sB = hasB ? d_csrc[j + 1] : sA;
        float2 elA = *(const float2*)&elb[(size_t)sA * 2];
        float2 elB = *(const float2*)&elb[(size_t)sB * 2];
        float wA0 = __expf(lrelu(elA.x + er2.x));
        float wA1 = __expf(lrelu(elA.y + er2.y));
        float wB0 = hasB ? __expf(lrelu(elB.x + er2.x)) : 0.f;
        float wB1 = hasB ? __expf(lrelu(elB.y + er2.y)) : 0.f;
        den0 += wA0 + wB0;
        den1 += wA1 + wB1;
        float2 hA = __half22float2(h2p[(size_t)sA * 32 + lane]);
        float2 hB = __half22float2(h2p[(size_t)sB * 32 + lane]);
        a0.x = fmaf(wA0, hA.x, fmaf(wB0, hB.x, a0.x));
        a0.y = fmaf(wA0, hA.y, fmaf(wB0, hB.y, a0.y));
        a1.x = fmaf(wA1, hA.x, fmaf(wB1, hB.x, a1.x));
        a1.y = fmaf(wA1, hA.y, fmaf(wB1, hB.y, a1.y));
    }
    float inv0 = (end > beg) ? 1.f / den0 : 0.f;
    float inv1 = (end > beg) ? 1.f / den1 : 0.f;
    __half2* p = (__half2*)&d_aggh[(size_t)row * 128];
    p[lane]      = __floats2half2_rn(a0.x * inv0, a0.y * inv0);
    p[32 + lane] = __floats2half2_rn(a1.x * inv1, a1.y * inv1);
}

// ===== out gemm 64 (layer 1): mma.sync m16n8k16 fp16 =====
// block: 64 nodes x 128 cols; warp w: m-rows (w&3)*16, head = w>>2 (64 cols)
__global__ void out_gemm64_kernel(const float* __restrict__ b,
                                  __half* __restrict__ hout) {
    constexpr int WS = 72;    // Ws stride (halves)
    constexpr int AS = 136;   // As stride (halves)
    __shared__ __align__(16) char sbuf[36864];
    __half* Ws = (__half*)sbuf;                     // 128 x 72 halves
    __half* As = (__half*)(sbuf + 128 * WS * 2);    // 64 x 136 halves
    float*  St = (float*)sbuf;                      // alias: 64 x 128 f32

    int tid = threadIdx.x;
    int warp = tid >> 5, lane = tid & 31;
    int g = lane >> 2, tg = lane & 3;
    int mrow = (warp & 3) * 16;
    int head = warp >> 2;
    int nbase = blockIdx.x * 64;
    int nvalid = min(64, NN - nbase);

    float acc[8][4];
#pragma unroll
    for (int i = 0; i < 8; i++)
#pragma unroll
        for (int j = 0; j < 4; j++) acc[i][j] = 0.f;

    for (int t = 0; t < TT; t++) {
        const uint4* wsrc = (const uint4*)(d_wt1 + (size_t)t * 128 * 64);
        for (int i = tid; i < 128 * 8; i += 256) {      // 8 uint4 per n-row
            int row = i >> 3, c = i & 7;
            *(uint4*)&Ws[row * WS + c * 8] = wsrc[i];
        }
        const uint4* asrc = (const uint4*)(d_aggh + ((size_t)t * NN + nbase) * 128);
        for (int i = tid; i < nvalid * 16; i += 256) {  // 16 uint4 per node
            int node = i >> 4, c = i & 15;
            *(uint4*)&As[node * AS + c * 8] = asrc[i];
        }
        __syncthreads();

        unsigned afr[4][4];
        const __half* Abase = As + (size_t)mrow * AS + head * 64;
#pragma unroll
        for (int k16 = 0; k16 < 4; k16++) {
            const __half* ab = Abase + k16 * 16;
            afr[k16][0] = *(const unsigned*)&ab[g * AS + tg * 2];
            afr[k16][1] = *(const unsigned*)&ab[(g + 8) * AS + tg * 2];
            afr[k16][2] = *(const unsigned*)&ab[g * AS + tg * 2 + 8];
            afr[k16][3] = *(const unsigned*)&ab[(g + 8) * AS + tg * 2 + 8];
        }
#pragma unroll
        for (int nt = 0; nt < 8; nt++) {
            const __half* wb = Ws + (size_t)(head * 64 + nt * 8 + g) * WS;
#pragma unroll
            for (int k16 = 0; k16 < 4; k16++) {
                unsigned b0 = *(const unsigned*)&wb[k16 * 16 + tg * 2];
                unsigned b1 = *(const unsigned*)&wb[k16 * 16 + tg * 2 + 8];
                MMA16816(acc[nt], afr[k16], b0, b1);
            }
        }
        __syncthreads();
    }

    // write result tile to St, then fused post
#pragma unroll
    for (int nt = 0; nt < 8; nt++) {
        int col = head * 64 + nt * 8 + tg * 2;
        St[(mrow + g) * 128 + col]     = acc[nt][0];
        St[(mrow + g) * 128 + col + 1] = acc[nt][1];
        St[(mrow + 8 + g) * 128 + col]     = acc[nt][2];
        St[(mrow + 8 + g) * 128 + col + 1] = acc[nt][3];
    }
    __syncthreads();

    int dd = tid & 63;
    int q = tid >> 6;
    float bm0 = 0.f, bm1 = 0.f;
#pragma unroll
    for (int t = 0; t < TT; t++) {
        bm0 += b[t * 128 + dd];
        bm1 += b[t * 128 + 64 + dd];
    }
    bm0 *= 0.25f; bm1 *= 0.25f;
#pragma unroll
    for (int i = 0; i < 16; i++) {
        int node = q * 16 + i;
        int n = nbase + node;
        if (n < NN) {
            float v0 = St[node * 128 + dd] * 0.25f + bm0;
            float v1 = St[node * 128 + 64 + dd] * 0.25f + bm1;
            v0 = fmaxf(v0, 0.f);
            v1 = fmaxf(v1, 0.f);
            float nrm = sqrtf(v0 * v0 + v1 * v1);
            float inv = 1.f / fmaxf(nrm, 1e-12f);
            hout[(size_t)n * 64 + dd] = __float2half(0.5f * (v0 + v1) * inv);
        }
    }
}

// ===== out gemm layer0 (K=23 -> padded 32): mma.sync m16n8k16 fp16 =====
__global__ void out_gemm23_kernel(const float* __restrict__ b,
                                  __half* __restrict__ hout) {
    constexpr int WS = 40;    // Ws stride (halves), k padded to 32
    constexpr int AS = 72;    // As stride (halves): 2 heads x 32
    constexpr int HS = 32;    // head stride in As
    __shared__ __align__(16) char sbuf[36864];
    __half* Ws = (__half*)sbuf;                     // 128 x 40 halves
    __half* As = (__half*)(sbuf + 128 * WS * 2);    // 64 x 72 halves
    float*  St = (float*)sbuf;                      // alias: 64 x 128 f32

    int tid = threadIdx.x;
    int warp = tid >> 5, lane = tid & 31;
    int g = lane >> 2, tg = lane & 3;
    int mrow = (warp & 3) * 16;
    int head = warp >> 2;
    int nbase = blockIdx.x * 64;
    int nvalid = min(64, NN - nbase);

    float acc[8][4];
#pragma unroll
    for (int i = 0; i < 8; i++)
#pragma unroll
        for (int j = 0; j < 4; j++) acc[i][j] = 0.f;

    for (int t = 0; t < TT; t++) {
        // W: 24 halves per n-row = 3 uint4; zero-pad halves 24..31
        const uint4* wsrc = (const uint4*)(d_wt0 + (size_t)t * 128 * 24);
        for (int i = tid; i < 128 * 3; i += 256) {
            int row = i / 3, c = i - row * 3;
            *(uint4*)&Ws[row * WS + c * 8] = wsrc[i];
        }
        for (int i = tid; i < 128; i += 256) {
            uint4 z = make_uint4(0u, 0u, 0u, 0u);
            *(uint4*)&Ws[i * WS + 24] = z;
        }
        // A: agg [node][48]: head0 k0..23, head1 k24..47 -> As[node][head][0..31]
        const __half* asrc = d_aggh + ((size_t)t * NN + nbase) * 48;
        for (int i = tid; i < nvalid * 64; i += 256) {
            int node = i >> 6, j = i & 63;
            int hh = j >> 5, k = j & 31;
            __half v = (k < 24) ? asrc[node * 48 + hh * 24 + k] : __float2half(0.f);
            As[node * AS + hh * HS + k] = v;
        }
        __syncthreads();

        unsigned afr[2][4];
        const __half* Abase = As + (size_t)mrow * AS + head * HS;
#pragma unroll
        for (int k16 = 0; k16 < 2; k16++) {
            const __half* ab = Abase + k16 * 16;
            afr[k16][0] = *(const unsigned*)&ab[g * AS + tg * 2];
            afr[k16][1] = *(const unsigned*)&ab[(g + 8) * AS + tg * 2];
            afr[k16][2] = *(const unsigned*)&ab[g * AS + tg * 2 + 8];
            afr[k16][3] = *(const unsigned*)&ab[(g + 8) * AS + tg * 2 + 8];
        }
#pragma unroll
        for (int nt = 0; nt < 8; nt++) {
            const __half* wb = Ws + (size_t)(head * 64 + nt * 8 + g) * WS;
#pragma unroll
            for (int k16 = 0; k16 < 2; k16++) {
                unsigned b0 = *(const unsigned*)&wb[k16 * 16 + tg * 2];
                unsigned b1 = *(const unsigned*)&wb[k16 * 16 + tg * 2 + 8];
                MMA16816(acc[nt], afr[k16], b0, b1);
            }
        }
        __syncthreads();
    }

#pragma unroll
    for (int nt = 0; nt < 8; nt++) {
        int col = head * 64 + nt * 8 + tg * 2;
        St[(mrow + g) * 128 + col]     = acc[nt][0];
        St[(mrow + g) * 128 + col + 1] = acc[nt][1];
        St[(mrow + 8 + g) * 128 + col]     = acc[nt][2];
        St[(mrow + 8 + g) * 128 + col + 1] = acc[nt][3];
    }
    __syncthreads();

    int dd = tid & 63;
    int q = tid >> 6;
    float bm0 = 0.f, bm1 = 0.f;
#pragma unroll
    for (int t = 0; t < TT; t++) {
        bm0 += b[t * 128 + dd];
        bm1 += b[t * 128 + 64 + dd];
    }
    bm0 *= 0.25f; bm1 *= 0.25f;
#pragma unroll
    for (int i = 0; i < 16; i++) {
        int node = q * 16 + i;
        int n = nbase + node;
        if (n < NN) {
            float v0 = St[node * 128 + dd] * 0.25f + bm0;
            float v1 = St[node * 128 + 64 + dd] * 0.25f + bm1;
            v0 = fmaxf(v0, 0.f);
            v1 = fmaxf(v1, 0.f);
            float nrm = sqrtf(v0 * v0 + v1 * v1);
            float inv = 1.f / fmaxf(nrm, 1e-12f);
            hout[(size_t)n * 64 + dd] = __float2half(0.5f * (v0 + v1) * inv);
        }
    }
}

// ==== layer 2 collapsed: node-mean of agg + final GEMM (last-block) ====
__global__ void aggmean_final_kernel(const float* __restrict__ W2,
                                     const float* __restrict__ b2,
                                     float* __restrict__ out) {
    int t = blockIdx.y;
    int col = threadIdx.x;   // 128
    float s = 0.f;
    for (int n = blockIdx.x; n < NN; n += gridDim.x)
        s += __half2float(d_aggh[((size_t)t * NN + n) * 128 + col]);
    atomicAdd(&d_msum[t * 128 + col], s);
    __threadfence();
    __syncthreads();
    __shared__ int flag;
    if (threadIdx.x == 0) {
        int v = atomicAdd(&d_ctr, 1);
        flag = (v == (int)(gridDim.x * gridDim.y) - 1);
    }
    __syncthreads();
    if (!flag) return;
    __threadfence();

    __shared__ float sm_m[512];
    for (int i = threadIdx.x; i < 512; i += 128) sm_m[i] = d_msum[i];
    __syncthreads();
    if (threadIdx.x < 64) {
        int dd = threadIdx.x;
        float sum = 0.f;
#pragma unroll
        for (int tt = 0; tt < TT; tt++)
#pragma unroll
            for (int hh = 0; hh < 2; hh++)
                for (int k = 0; k < 64; k++)
                    sum = fmaf(sm_m[tt * 128 + hh * 64 + k],
                               W2[((size_t)(tt * 64 + k)) * 128 + hh * 64 + dd], sum);
        sum *= 0.125f / (float)NN;
        float bb = 0.f;
#pragma unroll
        for (int tt = 0; tt < TT; tt++)
            bb += b2[tt * 128 + dd] + b2[tt * 128 + 64 + dd];
        out[dd] = sum + bb * 0.125f;
    }
}

// ================= driver =================
extern "C" void kernel_launch(void* const* d_in, const int* in_sizes, int n_in,
                              void* d_out, int out_size) {
    const float* x   = (const float*)d_in[0];
    const int* edges = (const int*)  d_in[1];
    const float* W0  = (const float*)d_in[2];
    const float* al0 = (const float*)d_in[3];
    const float* ar0 = (const float*)d_in[4];
    const float* b0  = (const float*)d_in[5];
    const float* W1  = (const float*)d_in[6];
    const float* al1 = (const float*)d_in[7];
    const float* ar1 = (const float*)d_in[8];
    const float* b1  = (const float*)d_in[9];
    const float* W2  = (const float*)d_in[10];
    const float* al2 = (const float*)d_in[11];
    const float* ar2 = (const float*)d_in[12];
    const float* b2  = (const float*)d_in[13];
    float* out = (float*)d_out;

    void* hptr = nullptr;
    cudaGetSymbolAddress(&hptr, d_hbuf);
    __half* h1 = (__half*)hptr;
    __half* h2 = h1 + (size_t)NN * 64;

    const int eg = (ETOT + 255) / 256;
    const int ng = (NN + 255) / 256;            // eler: thread per node
    const int sg = (ROWS * 32 + 255) / 256;     // segment: warp per row
    const int gg = (NN + 63) / 64;              // out gemm: 64-node tiles

    prep_kernel<<<256, 256>>>(W0, al0, ar0, W1, al1, ar1, W2, al2, ar2);
    hist_kernel<<<eg, 256>>>(edges);
    scan_k1<<<NBLK, 256>>>();
    scan_k3b<<<NBLK, 256>>>();
    scatter_kernel<<<eg, 256>>>(edges);

    // ---- layer 0 (K=23) ----
    eler23_kernel<<<ng, 256>>>(x);
    segment23_kernel<<<sg, 256>>>(x);
    out_gemm23_kernel<<<gg, 256>>>(b0, h1);

    // ---- layer 1 (K=64) ----
    eler64_kernel<<<ng, 256>>>(h1, 1);
    segment64_kernel<<<sg, 256>>>(h1);
    out_gemm64_kernel<<<gg, 256>>>(b1, h2);

    // ---- layer 2 (K=64, collapsed output) ----
    eler64_kernel<<<ng, 256>>>(h2, 2);
    segment64_kernel<<<sg, 256>>>(h2);
    {
        dim3 ag(512, TT);
        aggmean_final_kernel<<<ag, 128>>>(W2, b2, out);
    }
}